// round 1
// baseline (speedup 1.0000x reference)
#include <cuda_runtime.h>
#include <math.h>

// Problem constants
#define NBD 512
#define NS  256
#define NE  128

// smem strides (floats)
#define XS  132     // [row][e] tiles: 128 cols + 4 pad (16B-aligned rows, tc-lane banks distinct)
#define XWS 66      // XW^T [e][s]: 64 + 2 pad (even -> aligned 8B pairs, 2tc banks distinct)
#define PS  66      // P^T  [t][s]

#define SM_X   (128*XS)    // 16896 floats
#define SM_XWT (128*XWS)   //  8448
#define SM_U   (256*PS)    // 16896 (holds W 128x128=16384 in phase 0, P^T after)
#define SM_RM  (64*17)     //  1088
#define SM_TOT (SM_X + SM_XWT + SM_U + 2*SM_RM + 64)   // 44480 floats = 177920 B

__device__ __forceinline__ unsigned long long splat2(float x) {
    unsigned long long r;
    asm("mov.b64 %0, {%1, %1};" : "=l"(r) : "f"(x));
    return r;
}
__device__ __forceinline__ void fma2(unsigned long long& d, unsigned long long a, unsigned long long b) {
    asm("fma.rn.f32x2 %0, %1, %2, %0;" : "+l"(d) : "l"(a), "l"(b));
}
__device__ __forceinline__ float2 unpack2(unsigned long long v) {
    float2 r;
    asm("mov.b64 {%0, %1}, %2;" : "=f"(r.x), "=f"(r.y) : "l"(v));
    return r;
}

// Load `rows` x 128 fp32 tile (row-major, contiguous) into sX with stride XS.
// One warp loads one full row per step: coalesced 512B global reads, conflict-free STS.128.
__device__ __forceinline__ void load_tile(float* dst, const float* __restrict__ src, int rows, int tid) {
    const float4* s4 = (const float4*)src;
    int n4 = rows << 5;   // 32 float4 per row
    #pragma unroll 4
    for (int li = tid; li < n4; li += 256) {
        int r = li >> 5, c = li & 31;
        float4 v = s4[li];
        *(float4*)(dst + r * XS + (c << 2)) = v;
    }
}

__global__ void __launch_bounds__(256, 1)
sent_attn_kernel(const float* __restrict__ Xg, const float* __restrict__ Wg,
                 const int* __restrict__ lens, float* __restrict__ out)
{
    extern __shared__ float smem[];
    float* sX   = smem;              // key/value/query tile [128][XS]
    float* sXWT = sX + SM_X;         // XW^T [128 e][XWS]
    float* sU   = sXWT + SM_XWT;     // phase0: W [128][128] row-major; later: P^T [256][PS]
    float* sRm  = sU + SM_U;         // masked row-sum partials [64][17]
    float* sRz  = sRm + SM_RM;       // total  row-sum partials [64][17]
    float* sInv = sRz + SM_RM;       // 1/denom per row [64]

    const int tid = threadIdx.x;
    const int tr  = tid >> 4;        // 0..15
    const int tc  = tid & 15;        // 0..15
    const int s0  = tr << 2;         // local query row base (0..60), this thread owns rows s0..s0+3
    const int qbase = blockIdx.x << 6;   // query chunk base (0,64,128,192)
    const int bd    = blockIdx.y;        // sentence index 0..511
    const float* X  = Xg + (size_t)bd * (NS * NE);
    const int L     = lens[bd];

    // ---- load W into sU, query rows into sX ----
    {
        const float4* Wv = (const float4*)Wg;
        float4* sWv = (float4*)sU;
        #pragma unroll
        for (int j = 0; j < 16; ++j) sWv[tid + 256 * j] = Wv[tid + 256 * j];
    }
    load_tile(sX, X + qbase * NE, 64, tid);
    __syncthreads();

    // ---- phase 0: XW^T (64 queries x 128 feats), f paired via W rows ----
    {
        unsigned long long acc[4][4];
        #pragma unroll
        for (int i = 0; i < 4; ++i)
            #pragma unroll
            for (int j = 0; j < 4; ++j) acc[i][j] = 0ull;

        #pragma unroll 8
        for (int k = 0; k < NE; ++k) {
            unsigned long long as[4], b2[4];
            #pragma unroll
            for (int i = 0; i < 4; ++i) as[i] = splat2(sX[(s0 + i) * XS + k]);
            #pragma unroll
            for (int j = 0; j < 4; ++j)
                b2[j] = *(const unsigned long long*)(sU + k * 128 + 2 * tc + 32 * j);
            #pragma unroll
            for (int i = 0; i < 4; ++i)
                #pragma unroll
                for (int j = 0; j < 4; ++j) fma2(acc[i][j], as[i], b2[j]);
        }
        // store transposed: sXWT[f][s]
        #pragma unroll
        for (int i = 0; i < 4; ++i)
            #pragma unroll
            for (int j = 0; j < 4; ++j) {
                float2 v = unpack2(acc[i][j]);
                int f = 2 * tc + 32 * j;
                sXWT[f * XWS + s0 + i]       = v.x;
                sXWT[(f + 1) * XWS + s0 + i] = v.y;
            }
    }
    __syncthreads();   // phase-0 reads of sX/sU done; sXWT visible

    // ---- phase 1: logits -> tanh -> exp -> mask -> P^T in smem; row sums in regs ----
    float sumM[4] = {0.f, 0.f, 0.f, 0.f};
    float sumZ[4] = {0.f, 0.f, 0.f, 0.f};
    for (int kt = 0; kt < 2; ++kt) {
        load_tile(sX, X + kt * 128 * NE, 128, tid);
        __syncthreads();

        unsigned long long acc[2][8];   // [s-pair][t col], t_local = tc + 16*j
        #pragma unroll
        for (int p = 0; p < 2; ++p)
            #pragma unroll
            for (int j = 0; j < 8; ++j) acc[p][j] = 0ull;

        #pragma unroll 8
        for (int k = 0; k < NE; ++k) {   // k = e
            unsigned long long a2[2];
            a2[0] = *(const unsigned long long*)(sXWT + k * XWS + s0);
            a2[1] = *(const unsigned long long*)(sXWT + k * XWS + s0 + 2);
            #pragma unroll
            for (int j = 0; j < 8; ++j) {
                unsigned long long bs = splat2(sX[(tc + 16 * j) * XS + k]);
                fma2(acc[0][j], a2[0], bs);
                fma2(acc[1][j], a2[1], bs);
            }
        }
        // epilogue: tanh, exp, mask, write masked-e to P^T
        #pragma unroll
        for (int p = 0; p < 2; ++p)
            #pragma unroll
            for (int j = 0; j < 8; ++j) {
                float2 v = unpack2(acc[p][j]);
                int t = kt * 128 + tc + 16 * j;
                float e0 = __expf(tanhf(v.x));
                float e1 = __expf(tanhf(v.y));
                float m0 = (t < L) ? e0 : 0.f;
                float m1 = (t < L) ? e1 : 0.f;
                sumZ[2 * p]     += e0;  sumZ[2 * p + 1] += e1;
                sumM[2 * p]     += m0;  sumM[2 * p + 1] += m1;
                *(float2*)(sU + t * PS + s0 + 2 * p) = make_float2(m0, m1);
            }
        __syncthreads();   // protect sX reload next iter; P^T writes drain before phase 2
    }

    // ---- row-sum reduction: denom = Sm + 1e-8 * Z  (matches probs/(sum+1e-8)) ----
    #pragma unroll
    for (int i = 0; i < 4; ++i) {
        sRm[(s0 + i) * 17 + tc] = sumM[i];
        sRz[(s0 + i) * 17 + tc] = sumZ[i];
    }
    __syncthreads();
    if (tid < 64) {
        float sm = 0.f, sz = 0.f;
        #pragma unroll
        for (int c = 0; c < 16; ++c) { sm += sRm[tid * 17 + c]; sz += sRz[tid * 17 + c]; }
        sInv[tid] = 1.f / (sm + 1e-8f * sz);
    }
    __syncthreads();

    // ---- phase 2: att = P @ X, e paired ----
    unsigned long long acc[4][4];   // [s row][e pair], e = 2*tc + 32*j
    #pragma unroll
    for (int i = 0; i < 4; ++i)
        #pragma unroll
        for (int j = 0; j < 4; ++j) acc[i][j] = 0ull;

    for (int vt = 0; vt < 2; ++vt) {
        load_tile(sX, X + vt * 128 * NE, 128, tid);
        __syncthreads();
        #pragma unroll 8
        for (int k = 0; k < NE; ++k) {   // k = t local
            int t = vt * 128 + k;
            unsigned long long b2[4];
            #pragma unroll
            for (int j = 0; j < 4; ++j)
                b2[j] = *(const unsigned long long*)(sX + k * XS + 2 * tc + 32 * j);
            #pragma unroll
            for (int i = 0; i < 4; ++i) {
                unsigned long long as = splat2(sU[t * PS + s0 + i]);
                #pragma unroll
                for (int j = 0; j < 4; ++j) fma2(acc[i][j], as, b2[j]);
            }
        }
        __syncthreads();
    }

    // ---- write out with per-row renormalization ----
    float inv[4];
    #pragma unroll
    for (int i = 0; i < 4; ++i) inv[i] = sInv[s0 + i];
    #pragma unroll
    for (int i = 0; i < 4; ++i) {
        size_t row = (size_t)bd * NS + qbase + s0 + i;
        #pragma unroll
        for (int j = 0; j < 4; ++j) {
            float2 v = unpack2(acc[i][j]);
            v.x *= inv[i];
            v.y *= inv[i];
            *(float2*)(out + row * NE + 2 * tc + 32 * j) = v;
        }
    }
}

extern "C" void kernel_launch(void* const* d_in, const int* in_sizes, int n_in,
                              void* d_out, int out_size)
{
    const float* X    = (const float*)d_in[0];   // words_enc (8,64,256,128) f32
    const float* W    = (const float*)d_in[1];   // W (128,128) f32
    const int*   lens = (const int*)d_in[2];     // valid_words_len (8,64) i32
    float*       out  = (float*)d_out;           // (8,64,256,128) f32

    const size_t shmem = (size_t)SM_TOT * sizeof(float);   // 177920 B
    cudaFuncSetAttribute(sent_attn_kernel,
                         cudaFuncAttributeMaxDynamicSharedMemorySize, (int)shmem);
    dim3 grid(4, NBD, 1);   // 4 query chunks x 512 sentences
    dim3 block(256, 1, 1);
    sent_attn_kernel<<<grid, block, shmem>>>(X, W, lens, out);
}

// round 2
// speedup vs baseline: 1.2009x; 1.2009x over previous
#include <cuda_runtime.h>
#include <math.h>

#define NBD 512
#define NS  256
#define NE  128

// smem strides (floats) — chosen so bank stride of the fast-varying lane dim is 2 (conflict-free for 16 tc-lanes)
#define XS   130   // sX  [row][e] and sP share shape
#define WS   130   // sW  [k][f]
#define PS   130   // sP  [t][s]
#define XWS  132   // sXWT [e][s]: s contiguous; bank stride irrelevant (broadcast reads)

#define SM_X    (128*XS)
#define SM_WP   (128*PS)
#define SM_XWT  (128*XWS)
#define SM_RM   (128*17)
#define SM_TOT  (SM_X + SM_WP + SM_XWT + SM_RM + 128)   // 52480 floats = 209920 B

typedef unsigned long long u64;

__device__ __forceinline__ u64 splat2(float x) {
    u64 r; asm("mov.b64 %0, {%1, %1};" : "=l"(r) : "f"(x)); return r;
}
__device__ __forceinline__ u64 pack2(float a, float b) {
    u64 r; asm("mov.b64 %0, {%1, %2};" : "=l"(r) : "f"(a), "f"(b)); return r;
}
__device__ __forceinline__ void fma2(u64& d, u64 a, u64 b) {
    asm("fma.rn.f32x2 %0, %1, %2, %0;" : "+l"(d) : "l"(a), "l"(b));
}
__device__ __forceinline__ float2 unpack2(u64 v) {
    float2 r; asm("mov.b64 {%0, %1}, %2;" : "=f"(r.x), "=f"(r.y) : "l"(v)); return r;
}

// exp(tanh(x)) with fast intrinsics; saturates gracefully at +/-inf of e^{2x}
__device__ __forceinline__ float expTanh(float x) {
    float e2 = __expf(2.0f * x);
    float th = 1.0f - __fdividef(2.0f, e2 + 1.0f);
    return __expf(th);
}

// Load 128x128 fp32 tile (row-major contiguous) into smem with row stride 130.
// Coalesced LDG.128 + two conflict-free STS.64 per thread-item.
__device__ __forceinline__ void load_tile128(float* dst, const float* __restrict__ src, int tid) {
    const float4* s4 = (const float4*)src;
    #pragma unroll 4
    for (int li = tid; li < 4096; li += 256) {
        int r = li >> 5, c = li & 31;
        float4 v = s4[li];
        float* p = dst + r * XS + (c << 2);
        *(float2*)p       = make_float2(v.x, v.y);
        *(float2*)(p + 2) = make_float2(v.z, v.w);
    }
}

__global__ void __launch_bounds__(256, 1)
sent_attn_kernel(const float* __restrict__ Xg, const float* __restrict__ Wg,
                 const int* __restrict__ lens, float* __restrict__ out)
{
    extern __shared__ float smem[];
    float* sX   = smem;               // key/value/query tile [128][130]
    float* sWP  = sX + SM_X;          // phase0: W [128][130]; later P [t][130]
    float* sXWT = sWP + SM_WP;        // XW^T [e][132] (s contiguous)
    float* sRm  = sXWT + SM_XWT;      // row-sum partials [128][17]
    float* sInv = sRm + SM_RM;        // 1/denom [128]

    const int tid = threadIdx.x;
    const int tr  = tid >> 4;          // 0..15
    const int tc  = tid & 15;          // 0..15
    const int s0  = tr << 3;           // this thread's 8 query rows s0..s0+7
    const int qbase = blockIdx.x << 7; // 0 or 128
    const int bd    = blockIdx.y;
    const float* X  = Xg + (size_t)bd * (NS * NE);
    const int L     = lens[bd];

    // ---- load W and query tile ----
    load_tile128(sWP, Wg, tid);
    load_tile128(sX, X + qbase * NE, tid);
    __syncthreads();

    // ---- phase 0: XW^T  (xw[s,f] = sum_k x[s,k] W[k,f]), pairs along s, f = tc+16j ----
    {
        u64 acc0[4][8];
        #pragma unroll
        for (int p = 0; p < 4; ++p)
            #pragma unroll
            for (int j = 0; j < 8; ++j) acc0[p][j] = 0ull;

        #pragma unroll 4
        for (int k = 0; k < NE; ++k) {
            float av[8];
            #pragma unroll
            for (int i = 0; i < 8; ++i) av[i] = sX[(s0 + i) * XS + k];   // broadcast across tc
            u64 ap[4];
            #pragma unroll
            for (int p = 0; p < 4; ++p) ap[p] = pack2(av[2 * p], av[2 * p + 1]);
            #pragma unroll
            for (int j = 0; j < 8; ++j) {
                u64 bs = splat2(sWP[k * WS + tc + 16 * j]);              // conflict-free (bank 2k+tc)
                #pragma unroll
                for (int p = 0; p < 4; ++p) fma2(acc0[p][j], ap[p], bs);
            }
        }
        // store transposed: sXWT[f][s] as STS.64 s-pairs
        #pragma unroll
        for (int p = 0; p < 4; ++p)
            #pragma unroll
            for (int j = 0; j < 8; ++j) {
                float2 v = unpack2(acc0[p][j]);
                int f = tc + 16 * j;
                *(float2*)(sXWT + f * XWS + s0 + 2 * p) = v;
            }
    }
    __syncthreads();   // sXWT visible; phase-0 reads of sX/sWP done

    // ---- persistent att accumulators (8 s rows x 4 e-pairs) + masked row sums ----
    u64 acc2[8][4];
    #pragma unroll
    for (int i = 0; i < 8; ++i)
        #pragma unroll
        for (int j = 0; j < 4; ++j) acc2[i][j] = 0ull;
    float sumM[8] = {0.f, 0.f, 0.f, 0.f, 0.f, 0.f, 0.f, 0.f};

    const int nchunks = (L > 128) ? 2 : 1;   // skip keys beyond L (1e-8*Z term droppable: <=2e-5 rel)
    for (int ct = 0; ct < nchunks; ++ct) {
        load_tile128(sX, X + ct * 128 * NE, tid);
        __syncthreads();

        // phase 1: logits chunk (128 s x 128 t), pairs along s, t = tc+16j
        u64 acc1[4][8];
        #pragma unroll
        for (int p = 0; p < 4; ++p)
            #pragma unroll
            for (int j = 0; j < 8; ++j) acc1[p][j] = 0ull;

        #pragma unroll 2
        for (int k = 0; k < NE; ++k) {
            u64 ap[4];
            #pragma unroll
            for (int p = 0; p < 4; ++p)
                ap[p] = *(const u64*)(sXWT + k * XWS + s0 + 2 * p);      // LDS.64, broadcast
            #pragma unroll
            for (int j = 0; j < 8; ++j) {
                u64 bs = splat2(sX[(tc + 16 * j) * XS + k]);             // bank 2tc+k: conflict-free
                #pragma unroll
                for (int p = 0; p < 4; ++p) fma2(acc1[p][j], ap[p], bs);
            }
        }

        // epilogue: exp(tanh), mask, row-sum, stage P[t][s] (unnormalized)
        const int tbase = ct << 7;
        #pragma unroll
        for (int p = 0; p < 4; ++p)
            #pragma unroll
            for (int j = 0; j < 8; ++j) {
                float2 v = unpack2(acc1[p][j]);
                int tl = tc + 16 * j;
                float e0 = expTanh(v.x);
                float e1 = expTanh(v.y);
                if (tbase + tl >= L) { e0 = 0.f; e1 = 0.f; }
                sumM[2 * p]     += e0;
                sumM[2 * p + 1] += e1;
                *(float2*)(sWP + tl * PS + s0 + 2 * p) = make_float2(e0, e1);  // conflict-free STS.64
            }
        __syncthreads();   // sP complete

        // phase 2: att += P_chunk @ X_chunk, splat-a along s, pairs along e (e = 2tc+32j)
        #pragma unroll 2
        for (int tl = 0; tl < 128; ++tl) {
            u64 b2[4];
            #pragma unroll
            for (int j = 0; j < 4; ++j)
                b2[j] = *(const u64*)(sX + tl * XS + 2 * tc + 32 * j);   // LDS.64 conflict-free
            #pragma unroll
            for (int i = 0; i < 8; ++i) {
                u64 as = splat2(sWP[tl * PS + s0 + i]);                  // broadcast
                #pragma unroll
                for (int j = 0; j < 4; ++j) fma2(acc2[i][j], as, b2[j]);
            }
        }
        __syncthreads();   // done with sX/sP before next chunk overwrites
    }

    // ---- masked row-sum reduction -> inverse denominator ----
    #pragma unroll
    for (int i = 0; i < 8; ++i) sRm[(s0 + i) * 17 + tc] = sumM[i];
    __syncthreads();
    if (tid < 128) {
        float sm = 0.f;
        #pragma unroll
        for (int c = 0; c < 16; ++c) sm += sRm[tid * 17 + c];
        sInv[tid] = 1.0f / sm;
    }
    __syncthreads();

    // ---- output: renormalize and store ----
    #pragma unroll
    for (int i = 0; i < 8; ++i) {
        float inv = sInv[s0 + i];
        size_t row = (size_t)bd * NS + qbase + s0 + i;
        #pragma unroll
        for (int j = 0; j < 4; ++j) {
            float2 v = unpack2(acc2[i][j]);
            v.x *= inv; v.y *= inv;
            *(float2*)(out + row * NE + 2 * tc + 32 * j) = v;
        }
    }
}

extern "C" void kernel_launch(void* const* d_in, const int* in_sizes, int n_in,
                              void* d_out, int out_size)
{
    const float* X    = (const float*)d_in[0];   // words_enc (8,64,256,128) f32
    const float* W    = (const float*)d_in[1];   // W (128,128) f32
    const int*   lens = (const int*)d_in[2];     // valid_words_len (8,64) i32
    float*       out  = (float*)d_out;           // (8,64,256,128) f32

    const size_t shmem = (size_t)SM_TOT * sizeof(float);   // 209920 B
    cudaFuncSetAttribute(sent_attn_kernel,
                         cudaFuncAttributeMaxDynamicSharedMemorySize, (int)shmem);
    dim3 grid(2, NBD, 1);   // 2 query chunks x 512 sentences
    dim3 block(256, 1, 1);
    sent_attn_kernel<<<grid, block, shmem>>>(X, W, lens, out);
}

// round 3
// speedup vs baseline: 1.2017x; 1.0007x over previous
#include <cuda_runtime.h>
#include <math.h>

#define NBD 512
#define NS  256
#define NE  128

// smem strides (floats) — chosen so bank stride of the fast-varying lane dim is 2 (conflict-free for 16 tc-lanes)
#define XS   130   // sX  [row][e] and sP share shape
#define WS   130   // sW  [k][f]
#define PS   130   // sP  [t][s]
#define XWS  132   // sXWT [e][s]: s contiguous; bank stride irrelevant (broadcast reads)

#define SM_X    (128*XS)
#define SM_WP   (128*PS)
#define SM_XWT  (128*XWS)
#define SM_RM   (128*17)
#define SM_TOT  (SM_X + SM_WP + SM_XWT + SM_RM + 128)   // 52480 floats = 209920 B

typedef unsigned long long u64;

__device__ __forceinline__ u64 splat2(float x) {
    u64 r; asm("mov.b64 %0, {%1, %1};" : "=l"(r) : "f"(x)); return r;
}
__device__ __forceinline__ u64 pack2(float a, float b) {
    u64 r; asm("mov.b64 %0, {%1, %2};" : "=l"(r) : "f"(a), "f"(b)); return r;
}
__device__ __forceinline__ void fma2(u64& d, u64 a, u64 b) {
    asm("fma.rn.f32x2 %0, %1, %2, %0;" : "+l"(d) : "l"(a), "l"(b));
}
__device__ __forceinline__ float2 unpack2(u64 v) {
    float2 r; asm("mov.b64 {%0, %1}, %2;" : "=f"(r.x), "=f"(r.y) : "l"(v)); return r;
}

// exp(tanh(x)) with fast intrinsics; saturates gracefully at +/-inf of e^{2x}
__device__ __forceinline__ float expTanh(float x) {
    float e2 = __expf(2.0f * x);
    float th = 1.0f - __fdividef(2.0f, e2 + 1.0f);
    return __expf(th);
}

// Load 128x128 fp32 tile (row-major contiguous) into smem with row stride 130.
// Coalesced LDG.128 + two conflict-free STS.64 per thread-item.
__device__ __forceinline__ void load_tile128(float* dst, const float* __restrict__ src, int tid) {
    const float4* s4 = (const float4*)src;
    #pragma unroll 4
    for (int li = tid; li < 4096; li += 256) {
        int r = li >> 5, c = li & 31;
        float4 v = s4[li];
        float* p = dst + r * XS + (c << 2);
        *(float2*)p       = make_float2(v.x, v.y);
        *(float2*)(p + 2) = make_float2(v.z, v.w);
    }
}

__global__ void __launch_bounds__(256, 1)
sent_attn_kernel(const float* __restrict__ Xg, const float* __restrict__ Wg,
                 const int* __restrict__ lens, float* __restrict__ out)
{
    extern __shared__ float smem[];
    float* sX   = smem;               // key/value/query tile [128][130]
    float* sWP  = sX + SM_X;          // phase0: W [128][130]; later P [t][130]
    float* sXWT = sWP + SM_WP;        // XW^T [e][132] (s contiguous)
    float* sRm  = sXWT + SM_XWT;      // row-sum partials [128][17]
    float* sInv = sRm + SM_RM;        // 1/denom [128]

    const int tid = threadIdx.x;
    const int tr  = tid >> 4;          // 0..15
    const int tc  = tid & 15;          // 0..15
    const int s0  = tr << 3;           // this thread's 8 query rows s0..s0+7
    const int qbase = blockIdx.x << 7; // 0 or 128
    const int bd    = blockIdx.y;
    const float* X  = Xg + (size_t)bd * (NS * NE);
    const int L     = lens[bd];

    // ---- load W and query tile ----
    load_tile128(sWP, Wg, tid);
    load_tile128(sX, X + qbase * NE, tid);
    __syncthreads();

    // ---- phase 0: XW^T  (xw[s,f] = sum_k x[s,k] W[k,f]), pairs along s, f = tc+16j ----
    {
        u64 acc0[4][8];
        #pragma unroll
        for (int p = 0; p < 4; ++p)
            #pragma unroll
            for (int j = 0; j < 8; ++j) acc0[p][j] = 0ull;

        #pragma unroll 4
        for (int k = 0; k < NE; ++k) {
            float av[8];
            #pragma unroll
            for (int i = 0; i < 8; ++i) av[i] = sX[(s0 + i) * XS + k];   // broadcast across tc
            u64 ap[4];
            #pragma unroll
            for (int p = 0; p < 4; ++p) ap[p] = pack2(av[2 * p], av[2 * p + 1]);
            #pragma unroll
            for (int j = 0; j < 8; ++j) {
                u64 bs = splat2(sWP[k * WS + tc + 16 * j]);              // conflict-free (bank 2k+tc)
                #pragma unroll
                for (int p = 0; p < 4; ++p) fma2(acc0[p][j], ap[p], bs);
            }
        }
        // store transposed: sXWT[f][s] as STS.64 s-pairs
        #pragma unroll
        for (int p = 0; p < 4; ++p)
            #pragma unroll
            for (int j = 0; j < 8; ++j) {
                float2 v = unpack2(acc0[p][j]);
                int f = tc + 16 * j;
                *(float2*)(sXWT + f * XWS + s0 + 2 * p) = v;
            }
    }
    __syncthreads();   // sXWT visible; phase-0 reads of sX/sWP done

    // ---- persistent att accumulators (8 s rows x 4 e-pairs) + masked row sums ----
    u64 acc2[8][4];
    #pragma unroll
    for (int i = 0; i < 8; ++i)
        #pragma unroll
        for (int j = 0; j < 4; ++j) acc2[i][j] = 0ull;
    float sumM[8] = {0.f, 0.f, 0.f, 0.f, 0.f, 0.f, 0.f, 0.f};

    const int nchunks = (L > 128) ? 2 : 1;   // skip keys beyond L (1e-8*Z term droppable: <=2e-5 rel)
    for (int ct = 0; ct < nchunks; ++ct) {
        load_tile128(sX, X + ct * 128 * NE, tid);
        __syncthreads();

        // phase 1: logits chunk (128 s x 128 t), pairs along s, t = tc+16j
        u64 acc1[4][8];
        #pragma unroll
        for (int p = 0; p < 4; ++p)
            #pragma unroll
            for (int j = 0; j < 8; ++j) acc1[p][j] = 0ull;

        #pragma unroll 2
        for (int k = 0; k < NE; ++k) {
            u64 ap[4];
            #pragma unroll
            for (int p = 0; p < 4; ++p)
                ap[p] = *(const u64*)(sXWT + k * XWS + s0 + 2 * p);      // LDS.64, broadcast
            #pragma unroll
            for (int j = 0; j < 8; ++j) {
                u64 bs = splat2(sX[(tc + 16 * j) * XS + k]);             // bank 2tc+k: conflict-free
                #pragma unroll
                for (int p = 0; p < 4; ++p) fma2(acc1[p][j], ap[p], bs);
            }
        }

        // epilogue: exp(tanh), mask, row-sum, stage P[t][s] (unnormalized)
        const int tbase = ct << 7;
        #pragma unroll
        for (int p = 0; p < 4; ++p)
            #pragma unroll
            for (int j = 0; j < 8; ++j) {
                float2 v = unpack2(acc1[p][j]);
                int tl = tc + 16 * j;
                float e0 = expTanh(v.x);
                float e1 = expTanh(v.y);
                if (tbase + tl >= L) { e0 = 0.f; e1 = 0.f; }
                sumM[2 * p]     += e0;
                sumM[2 * p + 1] += e1;
                *(float2*)(sWP + tl * PS + s0 + 2 * p) = make_float2(e0, e1);  // conflict-free STS.64
            }
        __syncthreads();   // sP complete

        // phase 2: att += P_chunk @ X_chunk, splat-a along s, pairs along e (e = 2tc+32j)
        #pragma unroll 2
        for (int tl = 0; tl < 128; ++tl) {
            u64 b2[4];
            #pragma unroll
            for (int j = 0; j < 4; ++j)
                b2[j] = *(const u64*)(sX + tl * XS + 2 * tc + 32 * j);   // LDS.64 conflict-free
            #pragma unroll
            for (int i = 0; i < 8; ++i) {
                u64 as = splat2(sWP[tl * PS + s0 + i]);                  // broadcast
                #pragma unroll
                for (int j = 0; j < 4; ++j) fma2(acc2[i][j], as, b2[j]);
            }
        }
        __syncthreads();   // done with sX/sP before next chunk overwrites
    }

    // ---- masked row-sum reduction -> inverse denominator ----
    #pragma unroll
    for (int i = 0; i < 8; ++i) sRm[(s0 + i) * 17 + tc] = sumM[i];
    __syncthreads();
    if (tid < 128) {
        float sm = 0.f;
        #pragma unroll
        for (int c = 0; c < 16; ++c) sm += sRm[tid * 17 + c];
        sInv[tid] = 1.0f / sm;
    }
    __syncthreads();

    // ---- output: renormalize and store ----
    #pragma unroll
    for (int i = 0; i < 8; ++i) {
        float inv = sInv[s0 + i];
        size_t row = (size_t)bd * NS + qbase + s0 + i;
        #pragma unroll
        for (int j = 0; j < 4; ++j) {
            float2 v = unpack2(acc2[i][j]);
            v.x *= inv; v.y *= inv;
            *(float2*)(out + row * NE + 2 * tc + 32 * j) = v;
        }
    }
}

extern "C" void kernel_launch(void* const* d_in, const int* in_sizes, int n_in,
                              void* d_out, int out_size)
{
    const float* X    = (const float*)d_in[0];   // words_enc (8,64,256,128) f32
    const float* W    = (const float*)d_in[1];   // W (128,128) f32
    const int*   lens = (const int*)d_in[2];     // valid_words_len (8,64) i32
    float*       out  = (float*)d_out;           // (8,64,256,128) f32

    const size_t shmem = (size_t)SM_TOT * sizeof(float);   // 209920 B
    cudaFuncSetAttribute(sent_attn_kernel,
                         cudaFuncAttributeMaxDynamicSharedMemorySize, (int)shmem);
    dim3 grid(2, NBD, 1);   // 2 query chunks x 512 sentences
    dim3 block(256, 1, 1);
    sent_attn_kernel<<<grid, block, shmem>>>(X, W, lens, out);
}

// round 4
// speedup vs baseline: 1.2474x; 1.0380x over previous
#include <cuda_runtime.h>
#include <math.h>

#define NBD 512
#define NS  256
#define NE  128
#define ST  130   // smem row stride (floats): bank stride 2 -> k-paired LDS.64 conflict-free

#define SM_TILE (128*ST)
#define SM_RM   (128*17)
#define SM_TOT  (3*SM_TILE + SM_RM + 128 + 32)   // 52384 floats = 209536 B

typedef unsigned long long u64;

__device__ __forceinline__ void fma2(u64& d, u64 a, u64 b) {
    asm("fma.rn.f32x2 %0, %1, %2, %0;" : "+l"(d) : "l"(a), "l"(b));
}
__device__ __forceinline__ float fold2(u64 v) {
    float2 r;
    asm("mov.b64 {%0, %1}, %2;" : "=f"(r.x), "=f"(r.y) : "l"(v));
    return r.x + r.y;
}

// exp(tanh(x)) via fast intrinsics; saturates gracefully at +/-inf of e^{2x}
__device__ __forceinline__ float expTanh(float x) {
    float e2 = __expf(2.0f * x);
    float th = 1.0f - __fdividef(2.0f, e2 + 1.0f);
    return __expf(th);
}

// Load 128x128 fp32 tile (row-major contiguous) into smem with row stride ST.
__device__ __forceinline__ void load_tile128(float* dst, const float* __restrict__ src, int tid) {
    const float4* s4 = (const float4*)src;
    #pragma unroll 4
    for (int li = tid; li < 4096; li += 256) {
        int r = li >> 5, c = li & 31;
        float4 v = s4[li];
        float* p = dst + r * ST + (c << 2);
        *(float2*)p       = make_float2(v.x, v.y);
        *(float2*)(p + 2) = make_float2(v.z, v.w);
    }
}

__global__ void __launch_bounds__(256, 1)
sent_attn_kernel(const float* __restrict__ Xg, const float* __restrict__ Wg,
                 const int* __restrict__ lens, float* __restrict__ out)
{
    extern __shared__ float smem[];
    float* sA   = smem;                 // X tile [t][e] -> transposed in place to [e][t]
    float* sB   = sA + SM_TILE;         // W^T [f][k], later P [s][t]
    float* sC   = sB + SM_TILE;         // XW [s][e]
    float* sRm  = sC + SM_TILE;         // row-sum partials [128][17]
    float* sInv = sRm + SM_RM;          // 1/denom [128]

    const int tid = threadIdx.x;
    const int tg  = tid >> 4;           // 0..15 -> owns 8 query rows
    const int tc  = tid & 15;           // 0..15 -> owns cols tc+16j
    const int s0  = tg << 3;
    const int qbase = blockIdx.x << 7;  // 0 or 128
    const int bd    = blockIdx.y;
    const float* X  = Xg + (size_t)bd * (NS * NE);
    const int L     = lens[bd];

    // ---- load W transposed into sB[f][k] (coalesced LDG.32, 2-way-conflict STS) ----
    #pragma unroll 4
    for (int i = 0; i < 64; ++i) {
        int idx = tid + 256 * i;        // idx < 16384
        int k = idx >> 7, f = idx & 127;
        sB[f * ST + k] = Wg[idx];
    }
    // ---- load query tile into sA[s][e] ----
    load_tile128(sA, X + qbase * NE, tid);
    __syncthreads();

    u64 acc[64];

    // ================= phase 0: XW = Xq @ W -> sC[s][e] =================
    #pragma unroll
    for (int q = 0; q < 64; ++q) acc[q] = 0ull;
    #pragma unroll 2
    for (int k2 = 0; k2 < 64; ++k2) {
        u64 a[8], b[8];
        #pragma unroll
        for (int i = 0; i < 8; ++i) a[i] = *(const u64*)(sA + (s0 + i) * ST + 2 * k2);
        #pragma unroll
        for (int j = 0; j < 8; ++j) b[j] = *(const u64*)(sB + (tc + 16 * j) * ST + 2 * k2);
        #pragma unroll
        for (int i = 0; i < 8; ++i)
            #pragma unroll
            for (int j = 0; j < 8; ++j) fma2(acc[i * 8 + j], a[i], b[j]);
    }
    #pragma unroll
    for (int i = 0; i < 8; ++i)
        #pragma unroll
        for (int j = 0; j < 8; ++j)
            sC[(s0 + i) * ST + tc + 16 * j] = fold2(acc[i * 8 + j]);
    __syncthreads();   // sC visible; phase-0 reads of sA/sB done

    // persistent output accumulators + masked row sums
    float accO[64];
    #pragma unroll
    for (int q = 0; q < 64; ++q) accO[q] = 0.f;
    float sumM[8] = {0.f, 0.f, 0.f, 0.f, 0.f, 0.f, 0.f, 0.f};

    const int nchunks = (L > 128) ? 2 : 1;   // skip key chunks beyond L (1e-8*Z droppable: <=2e-5 rel)
    for (int ct = 0; ct < nchunks; ++ct) {
        load_tile128(sA, X + ct * 128 * NE, tid);
        __syncthreads();

        // ===== phase 1: logits = XW @ X^T (k = e, paired) =====
        #pragma unroll
        for (int q = 0; q < 64; ++q) acc[q] = 0ull;
        #pragma unroll 2
        for (int k2 = 0; k2 < 64; ++k2) {
            u64 a[8], b[8];
            #pragma unroll
            for (int i = 0; i < 8; ++i) a[i] = *(const u64*)(sC + (s0 + i) * ST + 2 * k2);
            #pragma unroll
            for (int j = 0; j < 8; ++j) b[j] = *(const u64*)(sA + (tc + 16 * j) * ST + 2 * k2);
            #pragma unroll
            for (int i = 0; i < 8; ++i)
                #pragma unroll
                for (int j = 0; j < 8; ++j) fma2(acc[i * 8 + j], a[i], b[j]);
        }

        // epilogue: exp(tanh), mask, row-sum, stage P[s][t] into sB
        const int tbase = ct << 7;
        #pragma unroll
        for (int i = 0; i < 8; ++i)
            #pragma unroll
            for (int j = 0; j < 8; ++j) {
                float lg = fold2(acc[i * 8 + j]);
                float e  = expTanh(lg);
                int t = tbase + tc + 16 * j;
                if (t >= L) e = 0.f;
                sumM[i] += e;
                sB[(s0 + i) * ST + tc + 16 * j] = e;   // conflict-free scalar STS
            }
        __syncthreads();   // P complete; phase-1 reads of sA done

        // ===== in-place transpose sA: [t][e] -> [e][t] =====
        {
            float tv[64];
            #pragma unroll
            for (int i = 0; i < 64; ++i) {
                int idx = tid + 256 * i;
                tv[i] = sA[(idx >> 7) * ST + (idx & 127)];
            }
            __syncthreads();
            #pragma unroll
            for (int i = 0; i < 64; ++i) {
                int idx = tid + 256 * i;
                sA[(idx & 127) * ST + (idx >> 7)] = tv[i];
            }
            __syncthreads();
        }

        // ===== phase 2: att += P @ X (k = t, paired) =====
        #pragma unroll
        for (int q = 0; q < 64; ++q) acc[q] = 0ull;
        #pragma unroll 2
        for (int t2 = 0; t2 < 64; ++t2) {
            u64 a[8], b[8];
            #pragma unroll
            for (int i = 0; i < 8; ++i) a[i] = *(const u64*)(sB + (s0 + i) * ST + 2 * t2);
            #pragma unroll
            for (int j = 0; j < 8; ++j) b[j] = *(const u64*)(sA + (tc + 16 * j) * ST + 2 * t2);
            #pragma unroll
            for (int i = 0; i < 8; ++i)
                #pragma unroll
                for (int j = 0; j < 8; ++j) fma2(acc[i * 8 + j], a[i], b[j]);
        }
        #pragma unroll
        for (int q = 0; q < 64; ++q) accO[q] += fold2(acc[q]);
        __syncthreads();   // done with sA/sB before next chunk
    }

    // ---- masked row-sum reduction -> inverse denominator ----
    #pragma unroll
    for (int i = 0; i < 8; ++i) sRm[(s0 + i) * 17 + tc] = sumM[i];
    __syncthreads();
    if (tid < 128) {
        float sm = 0.f;
        #pragma unroll
        for (int c = 0; c < 16; ++c) sm += sRm[tid * 17 + c];
        sInv[tid] = 1.0f / sm;
    }
    __syncthreads();

    // ---- output: renormalize and store ----
    #pragma unroll
    for (int i = 0; i < 8; ++i) {
        float inv = sInv[s0 + i];
        size_t row = (size_t)bd * NS + qbase + s0 + i;
        #pragma unroll
        for (int j = 0; j < 8; ++j)
            out[row * NE + tc + 16 * j] = accO[i * 8 + j] * inv;
    }
}

extern "C" void kernel_launch(void* const* d_in, const int* in_sizes, int n_in,
                              void* d_out, int out_size)
{
    const float* X    = (const float*)d_in[0];   // words_enc (8,64,256,128) f32
    const float* W    = (const float*)d_in[1];   // W (128,128) f32
    const int*   lens = (const int*)d_in[2];     // valid_words_len (8,64) i32
    float*       out  = (float*)d_out;           // (8,64,256,128) f32

    const size_t shmem = (size_t)SM_TOT * sizeof(float);   // 209536 B
    cudaFuncSetAttribute(sent_attn_kernel,
                         cudaFuncAttributeMaxDynamicSharedMemorySize, (int)shmem);
    dim3 grid(2, NBD, 1);
    dim3 block(256, 1, 1);
    sent_attn_kernel<<<grid, block, shmem>>>(X, W, lens, out);
}

// round 6
// speedup vs baseline: 2.3015x; 1.8451x over previous
#include <cuda_runtime.h>
#include <cuda_bf16.h>
#include <stdint.h>

#define NBD 512
#define NS  256
#define NE  128
#define SH  136                 // halves per smem tile row (272B = 17*16B)
#define TILE_B (128*SH*2)       // 34816 bytes per bf16 tile

// smem regions (byte offsets)
#define R_AH 0                  // Xq -> XW  (A operand) hi
#define R_AL (1*TILE_B)         //           lo
#define R_BH (2*TILE_B)         // W -> keys (B operand) hi
#define R_BL (3*TILE_B)
#define R_PH (4*TILE_B)         // P tiles hi
#define R_PL (5*TILE_B)
#define R_RM (6*TILE_B)         // 128*4 f32 row-sum partials
#define R_INV (R_RM + 2048)     // 128 f32
#define SMEM_BYTES (R_INV + 512 + 256)

typedef uint32_t u32;

__device__ __forceinline__ u32 sm2u(const void* p) {
    u32 a;
    asm("{ .reg .u64 t; cvta.to.shared.u64 t, %1; cvt.u32.u64 %0, t; }" : "=r"(a) : "l"(p));
    return a;
}
__device__ __forceinline__ u32 packbf(float a, float b) {
    return (u32)__bfloat16_as_ushort(__float2bfloat16(b)) << 16 |
           (u32)__bfloat16_as_ushort(__float2bfloat16(a));
}
__device__ __forceinline__ float bflo(float x) {   // residual after bf16 truncation
    return x - __bfloat162float(__float2bfloat16(x));
}
__device__ __forceinline__ float expTanh(float x) {
    float e2 = __expf(2.0f * x);
    float th = 1.0f - __fdividef(2.0f, e2 + 1.0f);
    return __expf(th);
}

__device__ __forceinline__ void ldsm_x4(u32* r, u32 a) {
    asm volatile("ldmatrix.sync.aligned.m8n8.x4.shared.b16 {%0,%1,%2,%3}, [%4];"
                 : "=r"(r[0]), "=r"(r[1]), "=r"(r[2]), "=r"(r[3]) : "r"(a));
}
__device__ __forceinline__ void ldsm_x2(u32* r, u32 a) {
    asm volatile("ldmatrix.sync.aligned.m8n8.x2.shared.b16 {%0,%1}, [%2];"
                 : "=r"(r[0]), "=r"(r[1]) : "r"(a));
}
__device__ __forceinline__ void ldsm_x2t(u32* r, u32 a) {
    asm volatile("ldmatrix.sync.aligned.m8n8.x2.trans.shared.b16 {%0,%1}, [%2];"
                 : "=r"(r[0]), "=r"(r[1]) : "r"(a));
}
__device__ __forceinline__ void mma_bf16(float* c, const u32* a, const u32* b) {
    asm volatile(
        "mma.sync.aligned.m16n8k16.row.col.f32.bf16.bf16.f32 "
        "{%0,%1,%2,%3}, {%4,%5,%6,%7}, {%8,%9}, {%0,%1,%2,%3};"
        : "+f"(c[0]), "+f"(c[1]), "+f"(c[2]), "+f"(c[3])
        : "r"(a[0]), "r"(a[1]), "r"(a[2]), "r"(a[3]), "r"(b[0]), "r"(b[1]));
}

// Convert a [128][128] f32 row-major tile into bf16 hi/lo smem tiles (row stride SH halves).
__device__ __forceinline__ void conv_tile(char* hi, char* lo, const float* __restrict__ src, int tid) {
    const float4* s4 = (const float4*)src;
    #pragma unroll 2
    for (int li = tid; li < 4096; li += 256) {
        int r = li >> 5, c4 = li & 31;
        float4 v = s4[li];
        uint2 h = make_uint2(packbf(v.x, v.y), packbf(v.z, v.w));
        uint2 l = make_uint2(packbf(bflo(v.x), bflo(v.y)), packbf(bflo(v.z), bflo(v.w)));
        int off = r * (SH * 2) + 8 * c4;
        *(uint2*)(hi + off) = h;
        *(uint2*)(lo + off) = l;
    }
}

// C[128x128] (+)= (Ah+Al)[128xk128] @ (Bh+Bl)^T, 3-split. Warp tile 64x32.
// TRANSB=0: B frags non-trans from storage [n][k]; TRANSB=1: trans from storage [k][n].
template<bool TRANSB>
__device__ __forceinline__ void gemm128(u32 sb, u32 offAh, u32 offBh,
                                        float c[4][4][4], int mg, int ng, int lane)
{
    const u32 dA = offAh;                        // lo at +TILE_B
    const u32 dB = offBh;
    const int rowa = 64 * mg + (lane & 15);
    const int acol = (lane >> 4) * 8;
    #pragma unroll
    for (int k0 = 0; k0 < 128; k0 += 16) {
        u32 ah[4][4], al[4][4];
        #pragma unroll
        for (int mt = 0; mt < 4; ++mt) {
            u32 ad = sb + dA + ((rowa + 16 * mt) * SH + k0 + acol) * 2;
            ldsm_x4(ah[mt], ad);
            ldsm_x4(al[mt], ad + TILE_B);
        }
        u32 bh[4][2], bl[4][2];
        #pragma unroll
        for (int nt = 0; nt < 4; ++nt) {
            int n0 = 32 * ng + 8 * nt;
            u32 bd2;
            if (TRANSB)
                bd2 = sb + dB + ((k0 + (lane & 15)) * SH + n0) * 2;
            else
                bd2 = sb + dB + ((n0 + (lane & 7)) * SH + k0 + (lane & 8)) * 2;
            if (TRANSB) { ldsm_x2t(bh[nt], bd2); ldsm_x2t(bl[nt], bd2 + TILE_B); }
            else        { ldsm_x2 (bh[nt], bd2); ldsm_x2 (bl[nt], bd2 + TILE_B); }
        }
        #pragma unroll
        for (int mt = 0; mt < 4; ++mt)
            #pragma unroll
            for (int nt = 0; nt < 4; ++nt) {
                mma_bf16(c[mt][nt], ah[mt], bh[nt]);
                mma_bf16(c[mt][nt], ah[mt], bl[nt]);
                mma_bf16(c[mt][nt], al[mt], bh[nt]);
            }
    }
}

__global__ void __launch_bounds__(256, 1)
sent_attn_hmma(const float* __restrict__ Xg, const float* __restrict__ Wg,
               const int* __restrict__ lens, float* __restrict__ out)
{
    extern __shared__ char sm[];
    const u32 sb = sm2u(sm);
    const int tid = threadIdx.x, lane = tid & 31, wid = tid >> 5;
    const int mg = wid >> 2, ng = wid & 3;          // warp tile: rows 64*mg.., cols 32*ng..
    const int g = lane >> 2, tig = lane & 3;
    const int qc = blockIdx.x, bd = blockIdx.y;
    const float* X = Xg + (size_t)bd * NS * NE;
    const int L = lens[bd];

    // ---- stage W (natural [e][f]) and Xq ([s][e]) as bf16 hi/lo ----
    conv_tile(sm + R_BH, sm + R_BL, Wg, tid);
    conv_tile(sm + R_AH, sm + R_AL, X + qc * 128 * NE, tid);
    __syncthreads();

    // ================= GEMM1: XW = Xq @ W  (B = W [e][f], trans) =================
    float c1[4][4][4];
    #pragma unroll
    for (int mt = 0; mt < 4; ++mt)
        #pragma unroll
        for (int nt = 0; nt < 4; ++nt)
            #pragma unroll
            for (int r = 0; r < 4; ++r) c1[mt][nt][r] = 0.f;
    gemm128<true>(sb, R_AH, R_BH, c1, mg, ng, lane);
    __syncthreads();   // all reads of Xq/W done

    // ---- epilogue 1: write XW hi/lo into region A (overwrite Xq) ----
    #pragma unroll
    for (int mt = 0; mt < 4; ++mt)
        #pragma unroll
        for (int nt = 0; nt < 4; ++nt)
            #pragma unroll
            for (int h = 0; h < 2; ++h) {
                int row = 64 * mg + 16 * mt + g + 8 * h;
                int col = 32 * ng + 8 * nt + 2 * tig;
                float v0 = c1[mt][nt][2 * h], v1 = c1[mt][nt][2 * h + 1];
                int off = (row * SH + col) * 2;
                *(u32*)(sm + R_AH + off) = packbf(v0, v1);
                *(u32*)(sm + R_AL + off) = packbf(bflo(v0), bflo(v1));
            }

    // ---- persistent output accums + row sums ----
    float c3[4][4][4];
    #pragma unroll
    for (int mt = 0; mt < 4; ++mt)
        #pragma unroll
        for (int nt = 0; nt < 4; ++nt)
            #pragma unroll
            for (int r = 0; r < 4; ++r) c3[mt][nt][r] = 0.f;
    float sumM[4][2];
    #pragma unroll
    for (int mt = 0; mt < 4; ++mt) { sumM[mt][0] = 0.f; sumM[mt][1] = 0.f; }

    const int nch = (L > 128) ? 2 : 1;   // keys beyond L contribute 0 (1e-8*Z droppable: <=2e-5 rel)
    for (int ct = 0; ct < nch; ++ct) {
        __syncthreads();                 // prior reads of region B (W or keys ct-1) done; epi1 writes visible
        conv_tile(sm + R_BH, sm + R_BL, X + ct * 128 * NE, tid);   // key tiles [t][e]
        __syncthreads();

        // ===== GEMM2: logits = XW @ keys^T  (B = keys [t][e], non-trans) =====
        float c2[4][4][4];
        #pragma unroll
        for (int mt = 0; mt < 4; ++mt)
            #pragma unroll
            for (int nt = 0; nt < 4; ++nt)
                #pragma unroll
                for (int r = 0; r < 4; ++r) c2[mt][nt][r] = 0.f;
        gemm128<false>(sb, R_AH, R_BH, c2, mg, ng, lane);

        // ---- epilogue 2: exp(tanh), mask, sums, P hi/lo -> region P ----
        #pragma unroll
        for (int mt = 0; mt < 4; ++mt)
            #pragma unroll
            for (int nt = 0; nt < 4; ++nt)
                #pragma unroll
                for (int h = 0; h < 2; ++h) {
                    int row = 64 * mg + 16 * mt + g + 8 * h;
                    int col = 32 * ng + 8 * nt + 2 * tig;    // key index within chunk
                    int t = ct * 128 + col;
                    float p0 = expTanh(c2[mt][nt][2 * h]);
                    float p1 = expTanh(c2[mt][nt][2 * h + 1]);
                    if (t     >= L) p0 = 0.f;
                    if (t + 1 >= L) p1 = 0.f;
                    sumM[mt][h] += p0 + p1;
                    int off = (row * SH + col) * 2;
                    *(u32*)(sm + R_PH + off) = packbf(p0, p1);
                    *(u32*)(sm + R_PL + off) = packbf(bflo(p0), bflo(p1));
                }
        __syncthreads();   // P complete

        // ===== GEMM3: att += P @ keys  (B = keys [t][e], trans) =====
        gemm128<true>(sb, R_PH, R_BH, c3, mg, ng, lane);
    }

    // ---- row-sum reduction: shfl over tig, partials over ng, invert ----
    #pragma unroll
    for (int mt = 0; mt < 4; ++mt)
        #pragma unroll
        for (int h = 0; h < 2; ++h) {
            float v = sumM[mt][h];
            v += __shfl_xor_sync(0xffffffffu, v, 1);
            v += __shfl_xor_sync(0xffffffffu, v, 2);
            if (tig == 0) {
                int row = 64 * mg + 16 * mt + g + 8 * h;
                ((float*)(sm + R_RM))[row * 4 + ng] = v;
            }
        }
    __syncthreads();
    if (tid < 128) {
        const float* rm = (const float*)(sm + R_RM);
        float s = rm[tid * 4] + rm[tid * 4 + 1] + rm[tid * 4 + 2] + rm[tid * 4 + 3];
        ((float*)(sm + R_INV))[tid] = 1.0f / s;
    }
    __syncthreads();

    // ---- output: renormalize, direct STG.64 ----
    float* obase = out + ((size_t)bd * NS + qc * 128) * NE;
    const float* invp = (const float*)(sm + R_INV);
    #pragma unroll
    for (int mt = 0; mt < 4; ++mt)
        #pragma unroll
        for (int h = 0; h < 2; ++h) {
            int row = 64 * mg + 16 * mt + g + 8 * h;
            float iv = invp[row];
            #pragma unroll
            for (int nt = 0; nt < 4; ++nt) {
                int col = 32 * ng + 8 * nt + 2 * tig;
                float2 v = make_float2(c3[mt][nt][2 * h] * iv, c3[mt][nt][2 * h + 1] * iv);
                *(float2*)(obase + row * NE + col) = v;
            }
        }
}

extern "C" void kernel_launch(void* const* d_in, const int* in_sizes, int n_in,
                              void* d_out, int out_size)
{
    const float* X    = (const float*)d_in[0];   // words_enc (8,64,256,128) f32
    const float* W    = (const float*)d_in[1];   // W (128,128) f32
    const int*   lens = (const int*)d_in[2];     // valid_words_len (8,64) i32
    float*       out  = (float*)d_out;           // (8,64,256,128) f32

    cudaFuncSetAttribute(sent_attn_hmma, cudaFuncAttributeMaxDynamicSharedMemorySize, SMEM_BYTES);
    dim3 grid(2, NBD, 1);
    dim3 block(256, 1, 1);
    sent_attn_hmma<<<grid, block, SMEM_BYTES>>>(X, W, lens, out);
}

// round 9
// speedup vs baseline: 3.3072x; 1.4370x over previous
#include <cuda_runtime.h>
#include <cuda_bf16.h>
#include <stdint.h>

#define NBD 512
#define NS  256
#define NE  128
#define SH   136                // halves per A/B tile row (272B)
#define PSTR 72                 // halves per P tile row (144B)
#define T_A  (64*SH*2)          // 17408 B per 64-row bf16 tile
#define T_P  (64*PSTR*2)        // 9216 B

// smem regions (byte offsets)
#define R_AH 0                  // Xq -> XW hi
#define R_AL (R_AH + T_A)
#define R_BH (R_AL + T_A)       // W chunk / key chunk hi
#define R_BL (R_BH + T_A)
#define R_PH (R_BL + T_A)       // P hi
#define R_PL (R_PH + T_P)
#define R_RM (R_PL + T_P)       // 64*4 f32 row-sum partials
#define R_INV (R_RM + 1024)     // 64 f32
#define SMEM_BYTES (R_INV + 256)   // 89,600 B -> 2 CTAs/SM

typedef uint32_t u32;

__device__ __forceinline__ u32 sm2u(const void* p) {
    u32 a;
    asm("{ .reg .u64 t; cvta.to.shared.u64 t, %1; cvt.u32.u64 %0, t; }" : "=r"(a) : "l"(p));
    return a;
}
__device__ __forceinline__ u32 packbf(float a, float b) {
    return (u32)__bfloat16_as_ushort(__float2bfloat16(b)) << 16 |
           (u32)__bfloat16_as_ushort(__float2bfloat16(a));
}
__device__ __forceinline__ float bflo(float x) {
    return x - __bfloat162float(__float2bfloat16(x));
}
// Accurate path (R6-measured 9.5e-6): exp(tanh(x)) = exp(1 - 2/(e^{2x}+1)); 3 MUFU + 1 FFMA.
__device__ __forceinline__ float expTanh(float x) {
    float e2 = __expf(2.0f * x);
    float th = 1.0f - __fdividef(2.0f, e2 + 1.0f);
    return __expf(th);
}
__device__ __forceinline__ void ldsm_x4(u32* r, u32 a) {
    asm volatile("ldmatrix.sync.aligned.m8n8.x4.shared.b16 {%0,%1,%2,%3}, [%4];"
                 : "=r"(r[0]), "=r"(r[1]), "=r"(r[2]), "=r"(r[3]) : "r"(a));
}
__device__ __forceinline__ void ldsm_x4t(u32* r, u32 a) {
    asm volatile("ldmatrix.sync.aligned.m8n8.x4.trans.shared.b16 {%0,%1,%2,%3}, [%4];"
                 : "=r"(r[0]), "=r"(r[1]), "=r"(r[2]), "=r"(r[3]) : "r"(a));
}
__device__ __forceinline__ void mma_bf16(float* c, const u32* a, u32 b0, u32 b1) {
    asm volatile(
        "mma.sync.aligned.m16n8k16.row.col.f32.bf16.bf16.f32 "
        "{%0,%1,%2,%3}, {%4,%5,%6,%7}, {%8,%9}, {%0,%1,%2,%3};"
        : "+f"(c[0]), "+f"(c[1]), "+f"(c[2]), "+f"(c[3])
        : "r"(a[0]), "r"(a[1]), "r"(a[2]), "r"(a[3]), "r"(b0), "r"(b1));
}

// Convert a [64][128] f32 row-major tile into bf16 hi/lo smem tiles (row stride SH halves).
__device__ __forceinline__ void conv64(char* hi, char* lo, const float* __restrict__ src, int tid) {
    const float4* s4 = (const float4*)src;
    #pragma unroll
    for (int it = 0; it < 8; ++it) {
        int li = tid + 256 * it;         // < 2048
        int r = li >> 5, c4 = li & 31;
        float4 v = s4[li];
        uint2 h = make_uint2(packbf(v.x, v.y), packbf(v.z, v.w));
        uint2 l = make_uint2(packbf(bflo(v.x), bflo(v.y)), packbf(bflo(v.z), bflo(v.w)));
        int off = r * (SH * 2) + 8 * c4;
        *(uint2*)(hi + off) = h;
        *(uint2*)(lo + off) = l;
    }
}

__global__ void __launch_bounds__(256, 2)
sent_attn_hmma2(const float* __restrict__ Xg, const float* __restrict__ Wg,
                const int* __restrict__ lens, float* __restrict__ out)
{
    extern __shared__ char sm[];
    const u32 sb = sm2u(sm);
    const int tid = threadIdx.x, lane = tid & 31, wid = tid >> 5;
    const int mg = wid >> 2, ng = wid & 3;        // warp tile rows 32*mg, cols 32*ng
    const int g = lane >> 2, tig = lane & 3;
    const int qc = blockIdx.x, bd = blockIdx.y;   // qc in 0..3 (64-query chunks)
    const float* X = Xg + (size_t)bd * NS * NE;
    const int L = lens[bd];

    const int arow = (lane & 15);
    const int acol8 = (lane >> 4) << 3;

    // ---- stage Xq [64][128] as bf16 hi/lo ----
    conv64(sm + R_AH, sm + R_AL, X + qc * 64 * NE, tid);

    // ================= GEMM1: XW = Xq @ W  (W in two 64-row K passes, trans B) =================
    float c1[2][4][4];
    #pragma unroll
    for (int mt = 0; mt < 2; ++mt)
        #pragma unroll
        for (int nt = 0; nt < 4; ++nt)
            #pragma unroll
            for (int r = 0; r < 4; ++r) c1[mt][nt][r] = 0.f;

    #pragma unroll
    for (int p = 0; p < 2; ++p) {
        __syncthreads();                                  // B region free
        conv64(sm + R_BH, sm + R_BL, Wg + p * 64 * NE, tid);
        __syncthreads();
        #pragma unroll
        for (int k0 = 0; k0 < 4; ++k0) {
            u32 ah[2][4], al[2][4];
            #pragma unroll
            for (int mt = 0; mt < 2; ++mt) {
                u32 ad = sb + R_AH + (u32)(((32 * mg + 16 * mt + arow) * SH + p * 64 + k0 * 16 + acol8) * 2);
                ldsm_x4(ah[mt], ad);
                ldsm_x4(al[mt], ad + T_A);
            }
            u32 bh[8], bl[8];
            {
                u32 b0 = sb + R_BH + (u32)(((k0 * 16 + arow) * SH + 32 * ng + acol8) * 2);
                ldsm_x4t(bh, b0); ldsm_x4t(bh + 4, b0 + 32);
                ldsm_x4t(bl, b0 + T_A); ldsm_x4t(bl + 4, b0 + T_A + 32);
            }
            #pragma unroll
            for (int mt = 0; mt < 2; ++mt)
                #pragma unroll
                for (int nt = 0; nt < 4; ++nt) {
                    mma_bf16(c1[mt][nt], ah[mt], bh[2 * nt], bh[2 * nt + 1]);
                    mma_bf16(c1[mt][nt], ah[mt], bl[2 * nt], bl[2 * nt + 1]);
                    mma_bf16(c1[mt][nt], al[mt], bh[2 * nt], bh[2 * nt + 1]);
                }
        }
    }
    __syncthreads();   // RACE FIX: sibling warps (same mg, other ng) read region A's
                       // full row-band in GEMM1; epi-1 writes below overwrite it.

    // ---- epilogue 1: XW hi/lo overwrite region A ----
    #pragma unroll
    for (int mt = 0; mt < 2; ++mt)
        #pragma unroll
        for (int nt = 0; nt < 4; ++nt)
            #pragma unroll
            for (int h = 0; h < 2; ++h) {
                int row = 32 * mg + 16 * mt + g + 8 * h;
                int col = 32 * ng + 8 * nt + 2 * tig;
                float v0 = c1[mt][nt][2 * h], v1 = c1[mt][nt][2 * h + 1];
                int off = (row * SH + col) * 2;
                *(u32*)(sm + R_AH + off) = packbf(v0, v1);
                *(u32*)(sm + R_AL + off) = packbf(bflo(v0), bflo(v1));
            }

    // ---- persistent accumulators ----
    float c3[2][4][4];
    #pragma unroll
    for (int mt = 0; mt < 2; ++mt)
        #pragma unroll
        for (int nt = 0; nt < 4; ++nt)
            #pragma unroll
            for (int r = 0; r < 4; ++r) c3[mt][nt][r] = 0.f;
    float sumM[2][2];
    sumM[0][0] = sumM[0][1] = sumM[1][0] = sumM[1][1] = 0.f;

    const int nch = min(4, (L + 63) >> 6);   // 64-key chunks; keys >= L contribute 0
    for (int ct = 0; ct < nch; ++ct) {
        __syncthreads();                     // epi1 writes done / prior GEMM3 B-reads done
        conv64(sm + R_BH, sm + R_BL, X + ct * 64 * NE, tid);   // keys [t][e]
        __syncthreads();

        // ===== GEMM2: logits[64q][64t] = XW @ keys^T (non-trans B, warp n-tile 16) =====
        float c2[2][2][4];
        #pragma unroll
        for (int mt = 0; mt < 2; ++mt)
            #pragma unroll
            for (int nt = 0; nt < 2; ++nt)
                #pragma unroll
                for (int r = 0; r < 4; ++r) c2[mt][nt][r] = 0.f;

        #pragma unroll
        for (int k0 = 0; k0 < 8; ++k0) {
            u32 ah[2][4], al[2][4];
            #pragma unroll
            for (int mt = 0; mt < 2; ++mt) {
                u32 ad = sb + R_AH + (u32)(((32 * mg + 16 * mt + arow) * SH + k0 * 16 + acol8) * 2);
                ldsm_x4(ah[mt], ad);
                ldsm_x4(al[mt], ad + T_A);
            }
            u32 bh[4], bl[4];
            {
                u32 bad = sb + R_BH + (u32)(((16 * ng + arow) * SH + k0 * 16 + acol8) * 2);
                ldsm_x4(bh, bad);
                ldsm_x4(bl, bad + T_A);
            }
            // non-trans x4 tile pairs: nt0 = {r0,r2}, nt1 = {r1,r3}
            #pragma unroll
            for (int mt = 0; mt < 2; ++mt)
                #pragma unroll
                for (int nt = 0; nt < 2; ++nt) {
                    mma_bf16(c2[mt][nt], ah[mt], bh[nt], bh[nt + 2]);
                    mma_bf16(c2[mt][nt], ah[mt], bl[nt], bl[nt + 2]);
                    mma_bf16(c2[mt][nt], al[mt], bh[nt], bh[nt + 2]);
                }
        }

        // ---- epilogue 2: exp(tanh), mask, row sums, P hi/lo ----
        #pragma unroll
        for (int mt = 0; mt < 2; ++mt)
            #pragma unroll
            for (int nt = 0; nt < 2; ++nt)
                #pragma unroll
                for (int h = 0; h < 2; ++h) {
                    int row = 32 * mg + 16 * mt + g + 8 * h;
                    int col = 16 * ng + 8 * nt + 2 * tig;
                    int t = ct * 64 + col;
                    float p0 = expTanh(c2[mt][nt][2 * h]);
                    float p1 = expTanh(c2[mt][nt][2 * h + 1]);
                    if (t     >= L) p0 = 0.f;
                    if (t + 1 >= L) p1 = 0.f;
                    sumM[mt][h] += p0 + p1;
                    int off = (row * PSTR + col) * 2;
                    *(u32*)(sm + R_PH + off) = packbf(p0, p1);
                    *(u32*)(sm + R_PL + off) = packbf(bflo(p0), bflo(p1));
                }
        __syncthreads();   // P complete (cross-warp k reads in GEMM3)

        // ===== GEMM3: att += P @ keys  (trans B over [t][e], k = 64) =====
        #pragma unroll
        for (int k0 = 0; k0 < 4; ++k0) {
            u32 ah[2][4], al[2][4];
            #pragma unroll
            for (int mt = 0; mt < 2; ++mt) {
                u32 ad = sb + R_PH + (u32)(((32 * mg + 16 * mt + arow) * PSTR + k0 * 16 + acol8) * 2);
                ldsm_x4(ah[mt], ad);
                ldsm_x4(al[mt], ad + T_P);
            }
            u32 bh[8], bl[8];
            {
                u32 b0 = sb + R_BH + (u32)(((k0 * 16 + arow) * SH + 32 * ng + acol8) * 2);
                ldsm_x4t(bh, b0); ldsm_x4t(bh + 4, b0 + 32);
                ldsm_x4t(bl, b0 + T_A); ldsm_x4t(bl + 4, b0 + T_A + 32);
            }
            #pragma unroll
            for (int mt = 0; mt < 2; ++mt)
                #pragma unroll
                for (int nt = 0; nt < 4; ++nt) {
                    mma_bf16(c3[mt][nt], ah[mt], bh[2 * nt], bh[2 * nt + 1]);
                    mma_bf16(c3[mt][nt], ah[mt], bl[2 * nt], bl[2 * nt + 1]);
                    mma_bf16(c3[mt][nt], al[mt], bh[2 * nt], bh[2 * nt + 1]);
                }
        }
    }

    // ---- row-sum reduction ----
    #pragma unroll
    for (int mt = 0; mt < 2; ++mt)
        #pragma unroll
        for (int h = 0; h < 2; ++h) {
            float v = sumM[mt][h];
            v += __shfl_xor_sync(0xffffffffu, v, 1);
            v += __shfl_xor_sync(0xffffffffu, v, 2);
            if (tig == 0) {
                int row = 32 * mg + 16 * mt + g + 8 * h;
                ((float*)(sm + R_RM))[row * 4 + ng] = v;
            }
        }
    __syncthreads();
    if (tid < 64) {
        const float* rm = (const float*)(sm + R_RM);
        float s = rm[tid * 4] + rm[tid * 4 + 1] + rm[tid * 4 + 2] + rm[tid * 4 + 3];
        ((float*)(sm + R_INV))[tid] = 1.0f / s;
    }
    __syncthreads();

    // ---- output: renormalize, STG.64 ----
    float* obase = out + ((size_t)bd * NS + qc * 64) * NE;
    const float* invp = (const float*)(sm + R_INV);
    #pragma unroll
    for (int mt = 0; mt < 2; ++mt)
        #pragma unroll
        for (int h = 0; h < 2; ++h) {
            int row = 32 * mg + 16 * mt + g + 8 * h;
            float iv = invp[row];
            #pragma unroll
            for (int nt = 0; nt < 4; ++nt) {
                int col = 32 * ng + 8 * nt + 2 * tig;
                float2 v = make_float2(c3[mt][nt][2 * h] * iv, c3[mt][nt][2 * h + 1] * iv);
                *(float2*)(obase + row * NE + col) = v;
            }
        }
}

extern "C" void kernel_launch(void* const* d_in, const int* in_sizes, int n_in,
                              void* d_out, int out_size)
{
    const float* X    = (const float*)d_in[0];   // words_enc (8,64,256,128) f32
    const float* W    = (const float*)d_in[1];   // W (128,128) f32
    const int*   lens = (const int*)d_in[2];     // valid_words_len (8,64) i32
    float*       out  = (float*)d_out;           // (8,64,256,128) f32

    cudaFuncSetAttribute(sent_attn_hmma2, cudaFuncAttributeMaxDynamicSharedMemorySize, SMEM_BYTES);
    dim3 grid(4, NBD, 1);   // 4 query chunks x 512 sentences
    dim3 block(256, 1, 1);
    sent_attn_hmma2<<<grid, block, SMEM_BYTES>>>(X, W, lens, out);
}

// round 10
// speedup vs baseline: 3.3768x; 1.0210x over previous
#include <cuda_runtime.h>
#include <cuda_bf16.h>
#include <stdint.h>

#define NBD 512
#define NS  256
#define NE  128
#define SH   136                // halves per A/B tile row (272B)
#define PSTR 72                 // halves per P tile row (144B)
#define T_A  (64*SH*2)          // 17408 B per 64-row bf16 tile
#define T_P  (64*PSTR*2)        // 9216 B

// smem regions (byte offsets)
#define R_AH 0                  // Xq -> XW hi
#define R_AL (R_AH + T_A)
#define R_BH (R_AL + T_A)       // W chunk / key chunk hi
#define R_BL (R_BH + T_A)       // (contiguous after R_BH)
#define R_PH (R_BL + T_A)       // P hi
#define R_PL (R_PH + T_P)
#define R_RM (R_PL + T_P)       // 64*4 f32 row-sum partials
#define R_INV (R_RM + 1024)     // 64 f32
#define R_STG (R_INV + 256)     // 16KB raw-f32 staging (16B aligned)
#define SMEM_BYTES (R_STG + 16384)   // 105,728 B -> 2 CTAs/SM (211.5KB)

typedef uint32_t u32;

// W preconverted: [pass p][hi image 17408B | lo image 17408B], byte-identical to B region
__device__ __align__(16) char g_Wbf[2][2 * T_A];

__device__ __forceinline__ u32 sm2u(const void* p) {
    u32 a;
    asm("{ .reg .u64 t; cvta.to.shared.u64 t, %1; cvt.u32.u64 %0, t; }" : "=r"(a) : "l"(p));
    return a;
}
__device__ __forceinline__ u32 packbf(float a, float b) {
    return (u32)__bfloat16_as_ushort(__float2bfloat16(b)) << 16 |
           (u32)__bfloat16_as_ushort(__float2bfloat16(a));
}
__device__ __forceinline__ float bflo(float x) {
    return x - __bfloat162float(__float2bfloat16(x));
}
// Accurate path (R6/R9-measured 9.5e-6): exp(tanh(x)) = exp(1 - 2/(e^{2x}+1)).
__device__ __forceinline__ float expTanh(float x) {
    float e2 = __expf(2.0f * x);
    float th = 1.0f - __fdividef(2.0f, e2 + 1.0f);
    return __expf(th);
}
__device__ __forceinline__ void ldsm_x4(u32* r, u32 a) {
    asm volatile("ldmatrix.sync.aligned.m8n8.x4.shared.b16 {%0,%1,%2,%3}, [%4];"
                 : "=r"(r[0]), "=r"(r[1]), "=r"(r[2]), "=r"(r[3]) : "r"(a));
}
__device__ __forceinline__ void ldsm_x4t(u32* r, u32 a) {
    asm volatile("ldmatrix.sync.aligned.m8n8.x4.trans.shared.b16 {%0,%1,%2,%3}, [%4];"
                 : "=r"(r[0]), "=r"(r[1]), "=r"(r[2]), "=r"(r[3]) : "r"(a));
}
__device__ __forceinline__ void mma_bf16(float* c, const u32* a, u32 b0, u32 b1) {
    asm volatile(
        "mma.sync.aligned.m16n8k16.row.col.f32.bf16.bf16.f32 "
        "{%0,%1,%2,%3}, {%4,%5,%6,%7}, {%8,%9}, {%0,%1,%2,%3};"
        : "+f"(c[0]), "+f"(c[1]), "+f"(c[2]), "+f"(c[3])
        : "r"(a[0]), "r"(a[1]), "r"(a[2]), "r"(a[3]), "r"(b0), "r"(b1));
}
__device__ __forceinline__ void cpa16(u32 smem, const void* g) {
    asm volatile("cp.async.cg.shared.global [%0], [%1], 16;" :: "r"(smem), "l"(g));
}
__device__ __forceinline__ void cpa_commit() { asm volatile("cp.async.commit_group;" ::: "memory"); }
template<int N> __device__ __forceinline__ void cpa_wait() {
    asm volatile("cp.async.wait_group %0;" :: "n"(N) : "memory");
}

// bf16-split convert one f32 quad into hi/lo tiles at (row r, col4 c4), row stride SH.
__device__ __forceinline__ void conv_quad(char* hi, char* lo, float4 v, int r, int c4) {
    uint2 h = make_uint2(packbf(v.x, v.y), packbf(v.z, v.w));
    uint2 l = make_uint2(packbf(bflo(v.x), bflo(v.y)), packbf(bflo(v.z), bflo(v.w)));
    int off = r * (SH * 2) + 8 * c4;
    *(uint2*)(hi + off) = h;
    *(uint2*)(lo + off) = l;
}

// Convert a [64][128] f32 row-major tile from GLOBAL into bf16 hi/lo smem tiles.
__device__ __forceinline__ void conv64(char* hi, char* lo, const float* __restrict__ src, int tid) {
    const float4* s4 = (const float4*)src;
    #pragma unroll
    for (int it = 0; it < 8; ++it) {
        int li = tid + 256 * it;
        conv_quad(hi, lo, s4[li], li >> 5, li & 31);
    }
}

// ---- prologue: W -> bf16 hi/lo images in g_Wbf (byte-identical to B region layout) ----
__global__ void conv_w_kernel(const float* __restrict__ Wg) {
    int idx = blockIdx.x * blockDim.x + threadIdx.x;
    if (idx >= 4096) return;                 // 2 passes x 2048 quads
    int p = idx >> 11, li = idx & 2047;
    int r = li >> 5, c4 = li & 31;
    const float4* s4 = (const float4*)(Wg + p * 64 * NE);
    float4 v = s4[li];
    uint2 h = make_uint2(packbf(v.x, v.y), packbf(v.z, v.w));
    uint2 l = make_uint2(packbf(bflo(v.x), bflo(v.y)), packbf(bflo(v.z), bflo(v.w)));
    int off = r * (SH * 2) + 8 * c4;
    *(uint2*)(g_Wbf[p] + off) = h;
    *(uint2*)(g_Wbf[p] + T_A + off) = l;
}

__global__ void __launch_bounds__(256, 2)
sent_attn_hmma2(const float* __restrict__ Xg, const float* __restrict__ Wg,
                const int* __restrict__ lens, float* __restrict__ out)
{
    extern __shared__ char sm[];
    const u32 sb = sm2u(sm);
    const int tid = threadIdx.x, lane = tid & 31, wid = tid >> 5;
    const int mg = wid >> 2, ng = wid & 3;        // warp tile rows 32*mg, cols 32*ng
    const int g = lane >> 2, tig = lane & 3;
    const int qc = blockIdx.x, bd = blockIdx.y;   // qc in 0..3 (64-query chunks)
    const float* X = Xg + (size_t)bd * NS * NE;
    const int L = lens[bd];

    const int arow = (lane & 15);
    const int acol8 = (lane >> 4) << 3;

    // ---- issue W pass-0 image copy (cp.async), overlap with Xq conversion ----
    for (int li = tid; li < 2176; li += 256)          // 34816B / 16
        cpa16(sb + R_BH + li * 16, g_Wbf[0] + li * 16);
    cpa_commit();
    conv64(sm + R_AH, sm + R_AL, X + qc * 64 * NE, tid);   // Xq (overlaps W0 copy)
    cpa_wait<0>();
    __syncthreads();                                   // A + B(W0) ready

    // ================= GEMM1: XW = Xq @ W  (two 64-row K passes, trans B) =================
    float c1[2][4][4];
    #pragma unroll
    for (int mt = 0; mt < 2; ++mt)
        #pragma unroll
        for (int nt = 0; nt < 4; ++nt)
            #pragma unroll
            for (int r = 0; r < 4; ++r) c1[mt][nt][r] = 0.f;

    #pragma unroll
    for (int p = 0; p < 2; ++p) {
        #pragma unroll
        for (int k0 = 0; k0 < 4; ++k0) {
            u32 ah[2][4], al[2][4];
            #pragma unroll
            for (int mt = 0; mt < 2; ++mt) {
                u32 ad = sb + R_AH + (u32)(((32 * mg + 16 * mt + arow) * SH + p * 64 + k0 * 16 + acol8) * 2);
                ldsm_x4(ah[mt], ad);
                ldsm_x4(al[mt], ad + T_A);
            }
            u32 bh[8], bl[8];
            {
                u32 b0 = sb + R_BH + (u32)(((k0 * 16 + arow) * SH + 32 * ng + acol8) * 2);
                ldsm_x4t(bh, b0); ldsm_x4t(bh + 4, b0 + 32);
                ldsm_x4t(bl, b0 + T_A); ldsm_x4t(bl + 4, b0 + T_A + 32);
            }
            #pragma unroll
            for (int mt = 0; mt < 2; ++mt)
                #pragma unroll
                for (int nt = 0; nt < 4; ++nt) {
                    mma_bf16(c1[mt][nt], ah[mt], bh[2 * nt], bh[2 * nt + 1]);
                    mma_bf16(c1[mt][nt], ah[mt], bl[2 * nt], bl[2 * nt + 1]);
                    mma_bf16(c1[mt][nt], al[mt], bh[2 * nt], bh[2 * nt + 1]);
                }
        }
        if (p == 0) {
            __syncthreads();                           // B(W0) reads done
            for (int li = tid; li < 2176; li += 256)   // W pass-1 image
                cpa16(sb + R_BH + li * 16, g_Wbf[1] + li * 16);
            cpa_commit();
            // prefetch key-chunk 0, rows 0-31 raw f32 (committed AFTER W1 so
            // wait<1> below releases on W1 while this may still fly)
            {
                const char* src = (const char*)X;
                #pragma unroll
                for (int i = 0; i < 4; ++i)
                    cpa16(sb + R_STG + (u32)((tid + 256 * i) * 16), src + (tid + 256 * i) * 16);
                cpa_commit();
            }
            cpa_wait<1>();                             // W1 arrived (stg0 may pend)
            __syncthreads();
        }
    }
    __syncthreads();   // RACE FIX: sibling warps read region A's full row-band in
                       // GEMM1; epi-1 writes below overwrite it.

    // ---- epilogue 1: XW hi/lo overwrite region A ----
    #pragma unroll
    for (int mt = 0; mt < 2; ++mt)
        #pragma unroll
        for (int nt = 0; nt < 4; ++nt)
            #pragma unroll
            for (int h = 0; h < 2; ++h) {
                int row = 32 * mg + 16 * mt + g + 8 * h;
                int col = 32 * ng + 8 * nt + 2 * tig;
                float v0 = c1[mt][nt][2 * h], v1 = c1[mt][nt][2 * h + 1];
                int off = (row * SH + col) * 2;
                *(u32*)(sm + R_AH + off) = packbf(v0, v1);
                *(u32*)(sm + R_AL + off) = packbf(bflo(v0), bflo(v1));
            }

    // ---- persistent accumulators ----
    float c3[2][4][4];
    #pragma unroll
    for (int mt = 0; mt < 2; ++mt)
        #pragma unroll
        for (int nt = 0; nt < 4; ++nt)
            #pragma unroll
            for (int r = 0; r < 4; ++r) c3[mt][nt][r] = 0.f;
    float sumM[2][2];
    sumM[0][0] = sumM[0][1] = sumM[1][0] = sumM[1][1] = 0.f;

    const int nch = min(4, (L + 63) >> 6);   // 64-key chunks; keys >= L contribute 0
    for (int ct = 0; ct < nch; ++ct) {
        __syncthreads();                     // epi1 visible / prior B,P reads done
        cpa_wait<0>();                       // staging(ct) arrived (self-addressed)

        // ---- convert chunk ct into B: rows 0-31 from staging, rows 32-63 direct LDG ----
        {
            const float4* s4g = (const float4*)(X + (ct * 64 + 32) * NE);
            float4 pre[4];
            #pragma unroll
            for (int i = 0; i < 4; ++i) pre[i] = s4g[tid + 256 * i];   // LDGs fly...
            const float4* st4 = (const float4*)(sm + R_STG);
            #pragma unroll
            for (int i = 0; i < 4; ++i) {                               // ...while staging converts
                int li = tid + 256 * i;
                conv_quad(sm + R_BH, sm + R_BL, st4[li], li >> 5, li & 31);
            }
            #pragma unroll
            for (int i = 0; i < 4; ++i) {
                int li = tid + 256 * i;
                conv_quad(sm + R_BH, sm + R_BL, pre[i], (li >> 5) + 32, li & 31);
            }
        }
        __syncthreads();                     // B ready (staging reads are self-addressed)

        // ---- prefetch next chunk's first 32 rows (overlaps GEMM2/epi2/GEMM3) ----
        if (ct + 1 < nch) {
            const char* src = (const char*)(X + (ct + 1) * 64 * NE);
            #pragma unroll
            for (int i = 0; i < 4; ++i)
                cpa16(sb + R_STG + (u32)((tid + 256 * i) * 16), src + (tid + 256 * i) * 16);
            cpa_commit();
        }

        // ===== GEMM2: logits[64q][64t] = XW @ keys^T (non-trans B, warp n-tile 16) =====
        float c2[2][2][4];
        #pragma unroll
        for (int mt = 0; mt < 2; ++mt)
            #pragma unroll
            for (int nt = 0; nt < 2; ++nt)
                #pragma unroll
                for (int r = 0; r < 4; ++r) c2[mt][nt][r] = 0.f;

        #pragma unroll
        for (int k0 = 0; k0 < 8; ++k0) {
            u32 ah[2][4], al[2][4];
            #pragma unroll
            for (int mt = 0; mt < 2; ++mt) {
                u32 ad = sb + R_AH + (u32)(((32 * mg + 16 * mt + arow) * SH + k0 * 16 + acol8) * 2);
                ldsm_x4(ah[mt], ad);
                ldsm_x4(al[mt], ad + T_A);
            }
            u32 bh[4], bl[4];
            {
                u32 bad = sb + R_BH + (u32)(((16 * ng + arow) * SH + k0 * 16 + acol8) * 2);
                ldsm_x4(bh, bad);
                ldsm_x4(bl, bad + T_A);
            }
            #pragma unroll
            for (int mt = 0; mt < 2; ++mt)
                #pragma unroll
                for (int nt = 0; nt < 2; ++nt) {
                    mma_bf16(c2[mt][nt], ah[mt], bh[nt], bh[nt + 2]);
                    mma_bf16(c2[mt][nt], ah[mt], bl[nt], bl[nt + 2]);
                    mma_bf16(c2[mt][nt], al[mt], bh[nt], bh[nt + 2]);
                }
        }

        // ---- epilogue 2: exp(tanh), mask, row sums, P hi/lo ----
        #pragma unroll
        for (int mt = 0; mt < 2; ++mt)
            #pragma unroll
            for (int nt = 0; nt < 2; ++nt)
                #pragma unroll
                for (int h = 0; h < 2; ++h) {
                    int row = 32 * mg + 16 * mt + g + 8 * h;
                    int col = 16 * ng + 8 * nt + 2 * tig;
                    int t = ct * 64 + col;
                    float p0 = expTanh(c2[mt][nt][2 * h]);
                    float p1 = expTanh(c2[mt][nt][2 * h + 1]);
                    if (t     >= L) p0 = 0.f;
                    if (t + 1 >= L) p1 = 0.f;
                    sumM[mt][h] += p0 + p1;
                    int off = (row * PSTR + col) * 2;
                    *(u32*)(sm + R_PH + off) = packbf(p0, p1);
                    *(u32*)(sm + R_PL + off) = packbf(bflo(p0), bflo(p1));
                }
        __syncthreads();   // P complete (cross-warp k reads in GEMM3)

        // ===== GEMM3: att += P @ keys  (trans B over [t][e], k = 64) =====
        #pragma unroll
        for (int k0 = 0; k0 < 4; ++k0) {
            u32 ah[2][4], al[2][4];
            #pragma unroll
            for (int mt = 0; mt < 2; ++mt) {
                u32 ad = sb + R_PH + (u32)(((32 * mg + 16 * mt + arow) * PSTR + k0 * 16 + acol8) * 2);
                ldsm_x4(ah[mt], ad);
                ldsm_x4(al[mt], ad + T_P);
            }
            u32 bh[8], bl[8];
            {
                u32 b0 = sb + R_BH + (u32)(((k0 * 16 + arow) * SH + 32 * ng + acol8) * 2);
                ldsm_x4t(bh, b0); ldsm_x4t(bh + 4, b0 + 32);
                ldsm_x4t(bl, b0 + T_A); ldsm_x4t(bl + 4, b0 + T_A + 32);
            }
            #pragma unroll
            for (int mt = 0; mt < 2; ++mt)
                #pragma unroll
                for (int nt = 0; nt < 4; ++nt) {
                    mma_bf16(c3[mt][nt], ah[mt], bh[2 * nt], bh[2 * nt + 1]);
                    mma_bf16(c3[mt][nt], ah[mt], bl[2 * nt], bl[2 * nt + 1]);
                    mma_bf16(c3[mt][nt], al[mt], bh[2 * nt], bh[2 * nt + 1]);
                }
        }
    }

    // ---- row-sum reduction ----
    #pragma unroll
    for (int mt = 0; mt < 2; ++mt)
        #pragma unroll
        for (int h = 0; h < 2; ++h) {
            float v = sumM[mt][h];
            v += __shfl_xor_sync(0xffffffffu, v, 1);
            v += __shfl_xor_sync(0xffffffffu, v, 2);
            if (tig == 0) {
                int row = 32 * mg + 16 * mt + g + 8 * h;
                ((float*)(sm + R_RM))[row * 4 + ng] = v;
            }
        }
    __syncthreads();
    if (tid < 64) {
        const float* rm = (const float*)(sm + R_RM);
        float s = rm[tid * 4] + rm[tid * 4 + 1] + rm[tid * 4 + 2] + rm[tid * 4 + 3];
        ((float*)(sm + R_INV))[tid] = 1.0f / s;
    }
    __syncthreads();

    // ---- output: renormalize, STG.64 ----
    float* obase = out + ((size_t)bd * NS + qc * 64) * NE;
    const float* invp = (const float*)(sm + R_INV);
    #pragma unroll
    for (int mt = 0; mt < 2; ++mt)
        #pragma unroll
        for (int h = 0; h < 2; ++h) {
            int row = 32 * mg + 16 * mt + g + 8 * h;
            float iv = invp[row];
            #pragma unroll
            for (int nt = 0; nt < 4; ++nt) {
                int col = 32 * ng + 8 * nt + 2 * tig;
                float2 v = make_float2(c3[mt][nt][2 * h] * iv, c3[mt][nt][2 * h + 1] * iv);
                *(float2*)(obase + row * NE + col) = v;
            }
        }
}

extern "C" void kernel_launch(void* const* d_in, const int* in_sizes, int n_in,
                              void* d_out, int out_size)
{
    const float* X    = (const float*)d_in[0];   // words_enc (8,64,256,128) f32
    const float* W    = (const float*)d_in[1];   // W (128,128) f32
    const int*   lens = (const int*)d_in[2];     // valid_words_len (8,64) i32
    float*       out  = (float*)d_out;           // (8,64,256,128) f32

    conv_w_kernel<<<16, 256>>>(W);               // preconvert W hi/lo images (70KB)

    cudaFuncSetAttribute(sent_attn_hmma2, cudaFuncAttributeMaxDynamicSharedMemorySize, SMEM_BYTES);
    dim3 grid(4, NBD, 1);   // 4 query chunks x 512 sentences
    dim3 block(256, 1, 1);
    sent_attn_hmma2<<<grid, block, SMEM_BYTES>>>(X, W, lens, out);
}

// round 11
// speedup vs baseline: 5.1394x; 1.5220x over previous
#include <cuda_runtime.h>
#include <cuda_fp16.h>
#include <stdint.h>

#define NBD 512
#define NS  256
#define NE  128
#define SH   136                // halves per A/B tile row (272B)
#define PSTR 72                 // halves per P tile row (144B)
#define T_A  (64*SH*2)          // 17408 B per 64-row fp16 tile
#define T_P  (64*PSTR*2)        // 9216 B

// smem regions (byte offsets). A-side (Xq/XW, P) is hi-only; B-side keeps hi+lo.
#define R_AH 0                  // Xq -> XW hi
#define R_BH (R_AH + T_A)       // W / key chunk hi
#define R_BL (R_BH + T_A)       // W / key chunk lo
#define R_PH (R_BL + T_A)       // P hi
#define R_RM (R_PH + T_P)       // 64*4 f32 row-sum partials
#define R_INV (R_RM + 1024)     // 64 f32
#define SMEM_BYTES (R_INV + 256)   // 62,720 B -> 3 CTAs/SM (188KB)

typedef uint32_t u32;

// W preconverted fp16 hi/lo images, byte-identical to B region layout
__device__ __align__(16) char g_Wbf[2][2 * T_A];

__device__ __forceinline__ u32 sm2u(const void* p) {
    u32 a;
    asm("{ .reg .u64 t; cvta.to.shared.u64 t, %1; cvt.u32.u64 %0, t; }" : "=r"(a) : "l"(p));
    return a;
}
__device__ __forceinline__ u32 packhf(float a, float b) {
    __half2 h = __floats2half2_rn(a, b);
    return *(u32*)&h;
}
__device__ __forceinline__ float hlo(float x) {   // residual after fp16 rn
    return x - __half2float(__float2half_rn(x));
}
// Accurate expTanh (R6/R9-measured chain): exp(1 - 2/(e^{2x}+1))
__device__ __forceinline__ float expTanh(float x) {
    float e2 = __expf(2.0f * x);
    float th = 1.0f - __fdividef(2.0f, e2 + 1.0f);
    return __expf(th);
}
__device__ __forceinline__ void ldsm_x4(u32* r, u32 a) {
    asm volatile("ldmatrix.sync.aligned.m8n8.x4.shared.b16 {%0,%1,%2,%3}, [%4];"
                 : "=r"(r[0]), "=r"(r[1]), "=r"(r[2]), "=r"(r[3]) : "r"(a));
}
__device__ __forceinline__ void ldsm_x4t(u32* r, u32 a) {
    asm volatile("ldmatrix.sync.aligned.m8n8.x4.trans.shared.b16 {%0,%1,%2,%3}, [%4];"
                 : "=r"(r[0]), "=r"(r[1]), "=r"(r[2]), "=r"(r[3]) : "r"(a));
}
__device__ __forceinline__ void mma_hf(float* c, const u32* a, u32 b0, u32 b1) {
    asm volatile(
        "mma.sync.aligned.m16n8k16.row.col.f32.f16.f16.f32 "
        "{%0,%1,%2,%3}, {%4,%5,%6,%7}, {%8,%9}, {%0,%1,%2,%3};"
        : "+f"(c[0]), "+f"(c[1]), "+f"(c[2]), "+f"(c[3])
        : "r"(a[0]), "r"(a[1]), "r"(a[2]), "r"(a[3]), "r"(b0), "r"(b1));
}
__device__ __forceinline__ void cpa16(u32 smem, const void* g) {
    asm volatile("cp.async.cg.shared.global [%0], [%1], 16;" :: "r"(smem), "l"(g));
}
__device__ __forceinline__ void cpa_commit() { asm volatile("cp.async.commit_group;" ::: "memory"); }
template<int N> __device__ __forceinline__ void cpa_wait() {
    asm volatile("cp.async.wait_group %0;" :: "n"(N) : "memory");
}

// Convert [64][128] f32 (global) -> fp16 hi+lo smem tiles (B-side)
__device__ __forceinline__ void conv64_hl(char* hi, char* lo, const float* __restrict__ src, int tid) {
    const float4* s4 = (const float4*)src;
    #pragma unroll
    for (int it = 0; it < 8; ++it) {
        int li = tid + 256 * it;
        int r = li >> 5, c4 = li & 31;
        float4 v = s4[li];
        uint2 h = make_uint2(packhf(v.x, v.y), packhf(v.z, v.w));
        uint2 l = make_uint2(packhf(hlo(v.x), hlo(v.y)), packhf(hlo(v.z), hlo(v.w)));
        int off = r * (SH * 2) + 8 * c4;
        *(uint2*)(hi + off) = h;
        *(uint2*)(lo + off) = l;
    }
}
// Convert [64][128] f32 (global) -> fp16 hi-only smem tile (A-side)
__device__ __forceinline__ void conv64_h(char* hi, const float* __restrict__ src, int tid) {
    const float4* s4 = (const float4*)src;
    #pragma unroll
    for (int it = 0; it < 8; ++it) {
        int li = tid + 256 * it;
        int r = li >> 5, c4 = li & 31;
        float4 v = s4[li];
        uint2 h = make_uint2(packhf(v.x, v.y), packhf(v.z, v.w));
        *(uint2*)(hi + r * (SH * 2) + 8 * c4) = h;
    }
}

// ---- prologue: W -> fp16 hi/lo images (byte-identical to B region layout) ----
__global__ void conv_w_kernel(const float* __restrict__ Wg) {
    int idx = blockIdx.x * blockDim.x + threadIdx.x;
    if (idx >= 4096) return;
    int p = idx >> 11, li = idx & 2047;
    int r = li >> 5, c4 = li & 31;
    const float4* s4 = (const float4*)(Wg + p * 64 * NE);
    float4 v = s4[li];
    uint2 h = make_uint2(packhf(v.x, v.y), packhf(v.z, v.w));
    uint2 l = make_uint2(packhf(hlo(v.x), hlo(v.y)), packhf(hlo(v.z), hlo(v.w)));
    int off = r * (SH * 2) + 8 * c4;
    *(uint2*)(g_Wbf[p] + off) = h;
    *(uint2*)(g_Wbf[p] + T_A + off) = l;
}

__global__ void __launch_bounds__(256, 3)
sent_attn_hmma3(const float* __restrict__ Xg, const float* __restrict__ Wg,
                const int* __restrict__ lens, float* __restrict__ out)
{
    extern __shared__ char sm[];
    const u32 sb = sm2u(sm);
    const int tid = threadIdx.x, lane = tid & 31, wid = tid >> 5;
    const int mg = wid >> 2, ng = wid & 3;        // warp tile rows 32*mg, cols 32*ng
    const int g = lane >> 2, tig = lane & 3;
    const int qc = blockIdx.x, bd = blockIdx.y;   // qc in 0..3 (64-query chunks)
    const float* X = Xg + (size_t)bd * NS * NE;
    const int L = lens[bd];

    const int arow = (lane & 15);
    const int acol8 = (lane >> 4) << 3;

    // ---- W pass-0 image via cp.async (hi+lo, 34816B), overlapped with Xq hi conversion ----
    for (int li = tid; li < 2176; li += 256)
        cpa16(sb + R_BH + li * 16, g_Wbf[0] + li * 16);
    cpa_commit();
    conv64_h(sm + R_AH, X + qc * 64 * NE, tid);
    cpa_wait<0>();
    __syncthreads();

    // ================= GEMM1: XW = Xq @ W (2-term: Ah*(Bh+Bl)), trans B =================
    float c1[2][4][4];
    #pragma unroll
    for (int mt = 0; mt < 2; ++mt)
        #pragma unroll
        for (int nt = 0; nt < 4; ++nt)
            #pragma unroll
            for (int r = 0; r < 4; ++r) c1[mt][nt][r] = 0.f;

    #pragma unroll
    for (int p = 0; p < 2; ++p) {
        #pragma unroll
        for (int k0 = 0; k0 < 4; ++k0) {
            u32 ah[2][4];
            #pragma unroll
            for (int mt = 0; mt < 2; ++mt)
                ldsm_x4(ah[mt], sb + R_AH + (u32)(((32 * mg + 16 * mt + arow) * SH + p * 64 + k0 * 16 + acol8) * 2));
            u32 bh[8], bl[8];
            {
                u32 b0 = sb + R_BH + (u32)(((k0 * 16 + arow) * SH + 32 * ng + acol8) * 2);
                ldsm_x4t(bh, b0); ldsm_x4t(bh + 4, b0 + 32);
                ldsm_x4t(bl, b0 + T_A); ldsm_x4t(bl + 4, b0 + T_A + 32);
            }
            #pragma unroll
            for (int mt = 0; mt < 2; ++mt)
                #pragma unroll
                for (int nt = 0; nt < 4; ++nt) {
                    mma_hf(c1[mt][nt], ah[mt], bh[2 * nt], bh[2 * nt + 1]);
                    mma_hf(c1[mt][nt], ah[mt], bl[2 * nt], bl[2 * nt + 1]);
                }
        }
        if (p == 0) {
            __syncthreads();                           // W0 reads done
            for (int li = tid; li < 2176; li += 256)
                cpa16(sb + R_BH + li * 16, g_Wbf[1] + li * 16);
            cpa_commit();
            cpa_wait<0>();
            __syncthreads();
        }
    }
    __syncthreads();   // RACE FIX: sibling warps read A's full row-band in GEMM1

    // ---- epilogue 1: XW hi overwrites region A ----
    #pragma unroll
    for (int mt = 0; mt < 2; ++mt)
        #pragma unroll
        for (int nt = 0; nt < 4; ++nt)
            #pragma unroll
            for (int h = 0; h < 2; ++h) {
                int row = 32 * mg + 16 * mt + g + 8 * h;
                int col = 32 * ng + 8 * nt + 2 * tig;
                *(u32*)(sm + R_AH + (row * SH + col) * 2) = packhf(c1[mt][nt][2 * h], c1[mt][nt][2 * h + 1]);
            }

    // ---- persistent accumulators ----
    float c3[2][4][4];
    #pragma unroll
    for (int mt = 0; mt < 2; ++mt)
        #pragma unroll
        for (int nt = 0; nt < 4; ++nt)
            #pragma unroll
            for (int r = 0; r < 4; ++r) c3[mt][nt][r] = 0.f;
    float sumM[2][2];
    sumM[0][0] = sumM[0][1] = sumM[1][0] = sumM[1][1] = 0.f;

    const int nch = min(4, (L + 63) >> 6);   // 64-key chunks; keys >= L contribute 0
    for (int ct = 0; ct < nch; ++ct) {
        __syncthreads();                     // epi1 visible / prior B,P reads done
        conv64_hl(sm + R_BH, sm + R_BL, X + ct * 64 * NE, tid);   // keys hi+lo
        __syncthreads();

        // ===== GEMM2: logits = XWh @ keys^T (2-term), non-trans B, n-tile 16 =====
        float c2[2][2][4];
        #pragma unroll
        for (int mt = 0; mt < 2; ++mt)
            #pragma unroll
            for (int nt = 0; nt < 2; ++nt)
                #pragma unroll
                for (int r = 0; r < 4; ++r) c2[mt][nt][r] = 0.f;

        #pragma unroll
        for (int k0 = 0; k0 < 8; ++k0) {
            u32 ah[2][4];
            #pragma unroll
            for (int mt = 0; mt < 2; ++mt)
                ldsm_x4(ah[mt], sb + R_AH + (u32)(((32 * mg + 16 * mt + arow) * SH + k0 * 16 + acol8) * 2));
            u32 bh[4], bl[4];
            {
                u32 bad = sb + R_BH + (u32)(((16 * ng + arow) * SH + k0 * 16 + acol8) * 2);
                ldsm_x4(bh, bad);
                ldsm_x4(bl, bad + T_A);
            }
            #pragma unroll
            for (int mt = 0; mt < 2; ++mt)
                #pragma unroll
                for (int nt = 0; nt < 2; ++nt) {
                    mma_hf(c2[mt][nt], ah[mt], bh[nt], bh[nt + 2]);
                    mma_hf(c2[mt][nt], ah[mt], bl[nt], bl[nt + 2]);
                }
        }

        // ---- epilogue 2: exp(tanh), mask, row sums, P hi ----
        #pragma unroll
        for (int mt = 0; mt < 2; ++mt)
            #pragma unroll
            for (int nt = 0; nt < 2; ++nt)
                #pragma unroll
                for (int h = 0; h < 2; ++h) {
                    int row = 32 * mg + 16 * mt + g + 8 * h;
                    int col = 16 * ng + 8 * nt + 2 * tig;
                    int t = ct * 64 + col;
                    float p0 = expTanh(c2[mt][nt][2 * h]);
                    float p1 = expTanh(c2[mt][nt][2 * h + 1]);
                    if (t     >= L) p0 = 0.f;
                    if (t + 1 >= L) p1 = 0.f;
                    sumM[mt][h] += p0 + p1;
                    *(u32*)(sm + R_PH + (row * PSTR + col) * 2) = packhf(p0, p1);
                }
        __syncthreads();   // P complete (cross-warp k reads in GEMM3)

        // ===== GEMM3: att += Ph @ keys (2-term), trans B, k = 64 =====
        #pragma unroll
        for (int k0 = 0; k0 < 4; ++k0) {
            u32 ah[2][4];
            #pragma unroll
            for (int mt = 0; mt < 2; ++mt)
                ldsm_x4(ah[mt], sb + R_PH + (u32)(((32 * mg + 16 * mt + arow) * PSTR + k0 * 16 + acol8) * 2));
            u32 bh[8], bl[8];
            {
                u32 b0 = sb + R_BH + (u32)(((k0 * 16 + arow) * SH + 32 * ng + acol8) * 2);
                ldsm_x4t(bh, b0); ldsm_x4t(bh + 4, b0 + 32);
                ldsm_x4t(bl, b0 + T_A); ldsm_x4t(bl + 4, b0 + T_A + 32);
            }
            #pragma unroll
            for (int mt = 0; mt < 2; ++mt)
                #pragma unroll
                for (int nt = 0; nt < 4; ++nt) {
                    mma_hf(c3[mt][nt], ah[mt], bh[2 * nt], bh[2 * nt + 1]);
                    mma_hf(c3[mt][nt], ah[mt], bl[2 * nt], bl[2 * nt + 1]);
                }
        }
    }

    // ---- row-sum reduction ----
    #pragma unroll
    for (int mt = 0; mt < 2; ++mt)
        #pragma unroll
        for (int h = 0; h < 2; ++h) {
            float v = sumM[mt][h];
            v += __shfl_xor_sync(0xffffffffu, v, 1);
            v += __shfl_xor_sync(0xffffffffu, v, 2);
            if (tig == 0) {
                int row = 32 * mg + 16 * mt + g + 8 * h;
                ((float*)(sm + R_RM))[row * 4 + ng] = v;
            }
        }
    __syncthreads();
    if (tid < 64) {
        const float* rm = (const float*)(sm + R_RM);
        float s = rm[tid * 4] + rm[tid * 4 + 1] + rm[tid * 4 + 2] + rm[tid * 4 + 3];
        ((float*)(sm + R_INV))[tid] = 1.0f / s;
    }
    __syncthreads();

    // ---- output: renormalize, STG.64 ----
    float* obase = out + ((size_t)bd * NS + qc * 64) * NE;
    const float* invp = (const float*)(sm + R_INV);
    #pragma unroll
    for (int mt = 0; mt < 2; ++mt)
        #pragma unroll
        for (int h = 0; h < 2; ++h) {
            int row = 32 * mg + 16 * mt + g + 8 * h;
            float iv = invp[row];
            #pragma unroll
            for (int nt = 0; nt < 4; ++nt) {
                int col = 32 * ng + 8 * nt + 2 * tig;
                float2 v = make_float2(c3[mt][nt][2 * h] * iv, c3[mt][nt][2 * h + 1] * iv);
                *(float2*)(obase + row * NE + col) = v;
            }
        }
}

extern "C" void kernel_launch(void* const* d_in, const int* in_sizes, int n_in,
                              void* d_out, int out_size)
{
    const float* X    = (const float*)d_in[0];   // words_enc (8,64,256,128) f32
    const float* W    = (const float*)d_in[1];   // W (128,128) f32
    const int*   lens = (const int*)d_in[2];     // valid_words_len (8,64) i32
    float*       out  = (float*)d_out;           // (8,64,256,128) f32

    conv_w_kernel<<<16, 256>>>(W);               // preconvert W fp16 hi/lo images

    cudaFuncSetAttribute(sent_attn_hmma3, cudaFuncAttributeMaxDynamicSharedMemorySize, SMEM_BYTES);
    dim3 grid(4, NBD, 1);   // 4 query chunks x 512 sentences
    dim3 block(256, 1, 1);
    sent_attn_hmma3<<<grid, block, SMEM_BYTES>>>(X, W, lens, out);
}

// round 12
// speedup vs baseline: 5.5400x; 1.0779x over previous
#include <cuda_runtime.h>
#include <cuda_fp16.h>
#include <stdint.h>

#define NBD 512
#define NS  256
#define NE  128
#define SH   136                // halves per A/B tile row (272B)
#define PSTR 72                 // halves per P tile row (144B)
#define T_A  (64*SH*2)          // 17408 B per 64-row fp16 tile
#define T_P  (64*PSTR*2)        // 9216 B

// smem regions (byte offsets). A-side (Xq/XW, P) hi-only; B-side hi+lo.
#define R_AH 0                  // Xq -> XW hi
#define R_BH (R_AH + T_A)       // W / key chunk hi
#define R_BL (R_BH + T_A)       // W / key chunk lo
#define R_PH (R_BL + T_A)       // P hi
#define R_RM (R_PH + T_P)       // 64*4 f32 row-sum partials
#define R_INV (R_RM + 1024)     // 64 f32
#define SMEM_BYTES (R_INV + 256)   // 62,720 B -> 3 CTAs/SM

typedef uint32_t u32;

// W preconverted fp16 hi/lo images, byte-identical to B region layout
__device__ __align__(16) char g_Wbf[2][2 * T_A];

__device__ __forceinline__ u32 sm2u(const void* p) {
    u32 a;
    asm("{ .reg .u64 t; cvta.to.shared.u64 t, %1; cvt.u32.u64 %0, t; }" : "=r"(a) : "l"(p));
    return a;
}
__device__ __forceinline__ u32 packhf(float a, float b) {
    __half2 h = __floats2half2_rn(a, b);
    return *(u32*)&h;
}
__device__ __forceinline__ float hlo(float x) {   // residual after fp16 rn
    return x - __half2float(__float2half_rn(x));
}
// Accurate expTanh (R6/R9-measured chain): exp(1 - 2/(e^{2x}+1))
__device__ __forceinline__ float expTanh(float x) {
    float e2 = __expf(2.0f * x);
    float th = 1.0f - __fdividef(2.0f, e2 + 1.0f);
    return __expf(th);
}
__device__ __forceinline__ void ldsm_x4(u32* r, u32 a) {
    asm volatile("ldmatrix.sync.aligned.m8n8.x4.shared.b16 {%0,%1,%2,%3}, [%4];"
                 : "=r"(r[0]), "=r"(r[1]), "=r"(r[2]), "=r"(r[3]) : "r"(a));
}
__device__ __forceinline__ void ldsm_x4t(u32* r, u32 a) {
    asm volatile("ldmatrix.sync.aligned.m8n8.x4.trans.shared.b16 {%0,%1,%2,%3}, [%4];"
                 : "=r"(r[0]), "=r"(r[1]), "=r"(r[2]), "=r"(r[3]) : "r"(a));
}
__device__ __forceinline__ void mma_hf(float* c, const u32* a, u32 b0, u32 b1) {
    asm volatile(
        "mma.sync.aligned.m16n8k16.row.col.f32.f16.f16.f32 "
        "{%0,%1,%2,%3}, {%4,%5,%6,%7}, {%8,%9}, {%0,%1,%2,%3};"
        : "+f"(c[0]), "+f"(c[1]), "+f"(c[2]), "+f"(c[3])
        : "r"(a[0]), "r"(a[1]), "r"(a[2]), "r"(a[3]), "r"(b0), "r"(b1));
}
__device__ __forceinline__ void cpa16(u32 smem, const void* g) {
    asm volatile("cp.async.cg.shared.global [%0], [%1], 16;" :: "r"(smem), "l"(g));
}
__device__ __forceinline__ void cpa_commit() { asm volatile("cp.async.commit_group;" ::: "memory"); }
template<int N> __device__ __forceinline__ void cpa_wait() {
    asm volatile("cp.async.wait_group %0;" :: "n"(N) : "memory");
}

// Convert [64][128] f32 (global) -> fp16 hi+lo smem tiles (B-side)
__device__ __forceinline__ void conv64_hl(char* hi, char* lo, const float* __restrict__ src, int tid) {
    const float4* s4 = (const float4*)src;
    #pragma unroll
    for (int it = 0; it < 8; ++it) {
        int li = tid + 256 * it;
        int r = li >> 5, c4 = li & 31;
        float4 v = s4[li];
        uint2 h = make_uint2(packhf(v.x, v.y), packhf(v.z, v.w));
        uint2 l = make_uint2(packhf(hlo(v.x), hlo(v.y)), packhf(hlo(v.z), hlo(v.w)));
        int off = r * (SH * 2) + 8 * c4;
        *(uint2*)(hi + off) = h;
        *(uint2*)(lo + off) = l;
    }
}
// Convert [64][128] f32 (global) -> fp16 hi-only smem tile (A-side)
__device__ __forceinline__ void conv64_h(char* hi, const float* __restrict__ src, int tid) {
    const float4* s4 = (const float4*)src;
    #pragma unroll
    for (int it = 0; it < 8; ++it) {
        int li = tid + 256 * it;
        int r = li >> 5, c4 = li & 31;
        float4 v = s4[li];
        uint2 h = make_uint2(packhf(v.x, v.y), packhf(v.z, v.w));
        *(uint2*)(hi + r * (SH * 2) + 8 * c4) = h;
    }
}

// ---- prologue: W -> fp16 hi/lo images (byte-identical to B region layout) ----
__global__ void conv_w_kernel(const float* __restrict__ Wg) {
    int idx = blockIdx.x * blockDim.x + threadIdx.x;
    if (idx >= 4096) return;
    int p = idx >> 11, li = idx & 2047;
    int r = li >> 5, c4 = li & 31;
    const float4* s4 = (const float4*)(Wg + p * 64 * NE);
    float4 v = s4[li];
    uint2 h = make_uint2(packhf(v.x, v.y), packhf(v.z, v.w));
    uint2 l = make_uint2(packhf(hlo(v.x), hlo(v.y)), packhf(hlo(v.z), hlo(v.w)));
    int off = r * (SH * 2) + 8 * c4;
    *(uint2*)(g_Wbf[p] + off) = h;
    *(uint2*)(g_Wbf[p] + T_A + off) = l;
}

__global__ void __launch_bounds__(256, 3)
sent_attn_hmma3(const float* __restrict__ Xg, const float* __restrict__ Wg,
                const int* __restrict__ lens, float* __restrict__ out)
{
    extern __shared__ char sm[];
    const u32 sb = sm2u(sm);
    const int tid = threadIdx.x, lane = tid & 31, wid = tid >> 5;
    const int mg = wid >> 2, ng = wid & 3;        // warp tile rows 32*mg, cols 32*ng
    const int g = lane >> 2, tig = lane & 3;
    const int qc = blockIdx.x, bd = blockIdx.y;   // qc in 0..3 (64-query chunks)
    const float* X = Xg + (size_t)bd * NS * NE;
    const int L = lens[bd];

    const int arow = (lane & 15);
    const int acol8 = (lane >> 4) << 3;

    // hoisted LDSM base addresses (loop-invariant; offsets become immediates)
    const u32 aA0 = sb + R_AH + (u32)(((32 * mg + arow) * SH + acol8) * 2);        // A rows, +16*mt*SH*2
    const u32 aB2 = sb + R_BH + (u32)(((16 * ng + arow) * SH + acol8) * 2);        // GEMM2 B (non-trans)
    const u32 aBT = sb + R_BH + (u32)((arow * SH + 32 * ng + acol8) * 2);          // GEMM1/3 B (trans), +k0*16*SH*2
    const u32 aP0 = sb + R_PH + (u32)(((32 * mg + arow) * PSTR + acol8) * 2);      // GEMM3 A (P)

    // ---- W pass-0 image via cp.async, overlapped with Xq hi conversion ----
    for (int li = tid; li < 2176; li += 256)
        cpa16(sb + R_BH + li * 16, g_Wbf[0] + li * 16);
    cpa_commit();
    conv64_h(sm + R_AH, X + qc * 64 * NE, tid);
    cpa_wait<0>();
    __syncthreads();

    // ================= GEMM1: XW = Xq @ W (2-term: Ah*(Bh+Bl)), trans B =================
    float c1[2][4][4];
    #pragma unroll
    for (int mt = 0; mt < 2; ++mt)
        #pragma unroll
        for (int nt = 0; nt < 4; ++nt)
            #pragma unroll
            for (int r = 0; r < 4; ++r) c1[mt][nt][r] = 0.f;

    #pragma unroll
    for (int p = 0; p < 2; ++p) {
        #pragma unroll
        for (int k0 = 0; k0 < 4; ++k0) {
            u32 ah[2][4];
            #pragma unroll
            for (int mt = 0; mt < 2; ++mt)
                ldsm_x4(ah[mt], aA0 + (u32)((16 * mt * SH + p * 64 + k0 * 16) * 2));
            u32 bh[8], bl[8];
            {
                u32 b0 = aBT + (u32)(k0 * 16 * SH * 2);
                ldsm_x4t(bh, b0); ldsm_x4t(bh + 4, b0 + 32);
                ldsm_x4t(bl, b0 + T_A); ldsm_x4t(bl + 4, b0 + T_A + 32);
            }
            #pragma unroll
            for (int mt = 0; mt < 2; ++mt)
                #pragma unroll
                for (int nt = 0; nt < 4; ++nt) {
                    mma_hf(c1[mt][nt], ah[mt], bh[2 * nt], bh[2 * nt + 1]);
                    mma_hf(c1[mt][nt], ah[mt], bl[2 * nt], bl[2 * nt + 1]);
                }
        }
        if (p == 0) {
            __syncthreads();                           // W0 reads done
            for (int li = tid; li < 2176; li += 256)
                cpa16(sb + R_BH + li * 16, g_Wbf[1] + li * 16);
            cpa_commit();
            cpa_wait<0>();
            __syncthreads();
        }
    }
    __syncthreads();   // RACE FIX: sibling warps read A's full row-band in GEMM1

    // ---- epilogue 1: XW hi overwrites region A ----
    #pragma unroll
    for (int mt = 0; mt < 2; ++mt)
        #pragma unroll
        for (int nt = 0; nt < 4; ++nt)
            #pragma unroll
            for (int h = 0; h < 2; ++h) {
                int row = 32 * mg + 16 * mt + g + 8 * h;
                int col = 32 * ng + 8 * nt + 2 * tig;
                *(u32*)(sm + R_AH + (row * SH + col) * 2) = packhf(c1[mt][nt][2 * h], c1[mt][nt][2 * h + 1]);
            }

    // ---- persistent accumulators ----
    float c3[2][4][4];
    #pragma unroll
    for (int mt = 0; mt < 2; ++mt)
        #pragma unroll
        for (int nt = 0; nt < 4; ++nt)
            #pragma unroll
            for (int r = 0; r < 4; ++r) c3[mt][nt][r] = 0.f;
    float sumM[2][2];
    sumM[0][0] = sumM[0][1] = sumM[1][0] = sumM[1][1] = 0.f;

    const int nch = min(4, (L + 63) >> 6);   // 64-key chunks; keys >= L contribute 0
    for (int ct = 0; ct < nch; ++ct) {
        __syncthreads();                     // epi1 visible / prior B,P reads done
        conv64_hl(sm + R_BH, sm + R_BL, X + ct * 64 * NE, tid);   // keys hi+lo
        __syncthreads();

        // ===== GEMM2: logits = XWh @ keys^T (2-term), non-trans B, n-tile 16 =====
        float c2[2][2][4];
        #pragma unroll
        for (int mt = 0; mt < 2; ++mt)
            #pragma unroll
            for (int nt = 0; nt < 2; ++nt)
                #pragma unroll
                for (int r = 0; r < 4; ++r) c2[mt][nt][r] = 0.f;

        #pragma unroll
        for (int k0 = 0; k0 < 8; ++k0) {
            u32 ah[2][4];
            #pragma unroll
            for (int mt = 0; mt < 2; ++mt)
                ldsm_x4(ah[mt], aA0 + (u32)((16 * mt * SH + k0 * 16) * 2));
            u32 bh[4], bl[4];
            {
                u32 bad = aB2 + (u32)(k0 * 16 * 2);
                ldsm_x4(bh, bad);
                ldsm_x4(bl, bad + T_A);
            }
            #pragma unroll
            for (int mt = 0; mt < 2; ++mt)
                #pragma unroll
                for (int nt = 0; nt < 2; ++nt) {
                    mma_hf(c2[mt][nt], ah[mt], bh[nt], bh[nt + 2]);
                    mma_hf(c2[mt][nt], ah[mt], bl[nt], bl[nt + 2]);
                }
        }

        // ---- epilogue 2: exp(tanh), mask, row sums, P hi ----
        #pragma unroll
        for (int mt = 0; mt < 2; ++mt)
            #pragma unroll
            for (int nt = 0; nt < 2; ++nt)
                #pragma unroll
                for (int h = 0; h < 2; ++h) {
                    int row = 32 * mg + 16 * mt + g + 8 * h;
                    int col = 16 * ng + 8 * nt + 2 * tig;
                    int t = ct * 64 + col;
                    float p0 = expTanh(c2[mt][nt][2 * h]);
                    float p1 = expTanh(c2[mt][nt][2 * h + 1]);
                    if (t     >= L) p0 = 0.f;
                    if (t + 1 >= L) p1 = 0.f;
                    sumM[mt][h] += p0 + p1;
                    *(u32*)(sm + R_PH + (row * PSTR + col) * 2) = packhf(p0, p1);
                }
        __syncthreads();   // P complete (cross-warp k reads in GEMM3)

        // ===== GEMM3: att += Ph @ keys-hi (single term — value residual linear in output,
        //        adds ~2e-4 rel, budget ok), trans B, k = 64 =====
        #pragma unroll
        for (int k0 = 0; k0 < 4; ++k0) {
            u32 ah[2][4];
            #pragma unroll
            for (int mt = 0; mt < 2; ++mt)
                ldsm_x4(ah[mt], aP0 + (u32)((16 * mt * PSTR + k0 * 16) * 2));
            u32 bh[8];
            {
                u32 b0 = aBT + (u32)(k0 * 16 * SH * 2);
                ldsm_x4t(bh, b0); ldsm_x4t(bh + 4, b0 + 32);
            }
            #pragma unroll
            for (int mt = 0; mt < 2; ++mt)
                #pragma unroll
                for (int nt = 0; nt < 4; ++nt)
                    mma_hf(c3[mt][nt], ah[mt], bh[2 * nt], bh[2 * nt + 1]);
        }
    }

    // ---- row-sum reduction ----
    #pragma unroll
    for (int mt = 0; mt < 2; ++mt)
        #pragma unroll
        for (int h = 0; h < 2; ++h) {
            float v = sumM[mt][h];
            v += __shfl_xor_sync(0xffffffffu, v, 1);
            v += __shfl_xor_sync(0xffffffffu, v, 2);
            if (tig == 0) {
                int row = 32 * mg + 16 * mt + g + 8 * h;
                ((float*)(sm + R_RM))[row * 4 + ng] = v;
            }
        }
    __syncthreads();
    if (tid < 64) {
        const float* rm = (const float*)(sm + R_RM);
        float s = rm[tid * 4] + rm[tid * 4 + 1] + rm[tid * 4 + 2] + rm[tid * 4 + 3];
        ((float*)(sm + R_INV))[tid] = 1.0f / s;
    }
    __syncthreads();

    // ---- output: renormalize, STG.64 ----
    float* obase = out + ((size_t)bd * NS + qc * 64) * NE;
    const float* invp = (const float*)(sm + R_INV);
    #pragma unroll
    for (int mt = 0; mt < 2; ++mt)
        #pragma unroll
        for (int h = 0; h < 2; ++h) {
            int row = 32 * mg + 16 * mt + g + 8 * h;
            float iv = invp[row];
            #pragma unroll
            for (int nt = 0; nt < 4; ++nt) {
                int col = 32 * ng + 8 * nt + 2 * tig;
                float2 v = make_float2(c3[mt][nt][2 * h] * iv, c3[mt][nt][2 * h + 1] * iv);
                *(float2*)(obase + row * NE + col) = v;
            }
        }
}

extern "C" void kernel_launch(void* const* d_in, const int* in_sizes, int n_in,
                              void* d_out, int out_size)
{
    const float* X    = (const float*)d_in[0];   // words_enc (8,64,256,128) f32
    const float* W    = (const float*)d_in[1];   // W (128,128) f32
    const int*   lens = (const int*)d_in[2];     // valid_words_len (8,64) i32
    float*       out  = (float*)d_out;           // (8,64,256,128) f32

    conv_w_kernel<<<16, 256>>>(W);               // preconvert W fp16 hi/lo images

    cudaFuncSetAttribute(sent_attn_hmma3, cudaFuncAttributeMaxDynamicSharedMemorySize, SMEM_BYTES);
    dim3 grid(4, NBD, 1);   // 4 query chunks x 512 sentences
    dim3 block(256, 1, 1);
    sent_attn_hmma3<<<grid, block, SMEM_BYTES>>>(X, W, lens, out);
}

// round 13
// speedup vs baseline: 5.5933x; 1.0096x over previous
#include <cuda_runtime.h>
#include <cuda_fp16.h>
#include <stdint.h>

#define NBD 512
#define NS  256
#define NE  128
#define SH   136                // halves per A/B tile row (272B)
#define PSTR 72                 // halves per P tile row (144B)
#define T_A  (64*SH*2)          // 17408 B per 64-row fp16 tile
#define T_P  (64*PSTR*2)        // 9216 B

// smem regions (byte offsets). A-side (Xq/XW, P) hi-only; keys hi+lo; W hi-only.
#define R_AH 0                  // Xq -> XW hi
#define R_BH (R_AH + T_A)       // W / key chunk hi
#define R_BL (R_BH + T_A)       // key chunk lo
#define R_PH (R_BL + T_A)       // P hi
#define R_RM (R_PH + T_P)       // 64*4 f32 row-sum partials
#define R_INV (R_RM + 1024)     // 64 f32
#define SMEM_BYTES (R_INV + 256)   // 62,720 B -> 3 CTAs/SM

typedef uint32_t u32;

// W preconverted fp16 hi images (lo dropped: W-side residual ~2.5e-4, budget ok)
__device__ __align__(16) char g_Wbf[2][T_A];

__device__ __forceinline__ u32 sm2u(const void* p) {
    u32 a;
    asm("{ .reg .u64 t; cvta.to.shared.u64 t, %1; cvt.u32.u64 %0, t; }" : "=r"(a) : "l"(p));
    return a;
}
__device__ __forceinline__ u32 packhf(float a, float b) {
    __half2 h = __floats2half2_rn(a, b);
    return *(u32*)&h;
}
__device__ __forceinline__ float hlo(float x) {   // residual after fp16 rn
    return x - __half2float(__float2half_rn(x));
}
// Accurate expTanh (R6/R9-measured chain): exp(1 - 2/(e^{2x}+1))
__device__ __forceinline__ float expTanh(float x) {
    float e2 = __expf(2.0f * x);
    float th = 1.0f - __fdividef(2.0f, e2 + 1.0f);
    return __expf(th);
}
__device__ __forceinline__ void ldsm_x4(u32* r, u32 a) {
    asm volatile("ldmatrix.sync.aligned.m8n8.x4.shared.b16 {%0,%1,%2,%3}, [%4];"
                 : "=r"(r[0]), "=r"(r[1]), "=r"(r[2]), "=r"(r[3]) : "r"(a));
}
__device__ __forceinline__ void ldsm_x4t(u32* r, u32 a) {
    asm volatile("ldmatrix.sync.aligned.m8n8.x4.trans.shared.b16 {%0,%1,%2,%3}, [%4];"
                 : "=r"(r[0]), "=r"(r[1]), "=r"(r[2]), "=r"(r[3]) : "r"(a));
}
__device__ __forceinline__ void mma_hf(float* c, const u32* a, u32 b0, u32 b1) {
    asm volatile(
        "mma.sync.aligned.m16n8k16.row.col.f32.f16.f16.f32 "
        "{%0,%1,%2,%3}, {%4,%5,%6,%7}, {%8,%9}, {%0,%1,%2,%3};"
        : "+f"(c[0]), "+f"(c[1]), "+f"(c[2]), "+f"(c[3])
        : "r"(a[0]), "r"(a[1]), "r"(a[2]), "r"(a[3]), "r"(b0), "r"(b1));
}
__device__ __forceinline__ void cpa16(u32 smem, const void* g) {
    asm volatile("cp.async.cg.shared.global [%0], [%1], 16;" :: "r"(smem), "l"(g));
}
__device__ __forceinline__ void cpa_commit() { asm volatile("cp.async.commit_group;" ::: "memory"); }
template<int N> __device__ __forceinline__ void cpa_wait() {
    asm volatile("cp.async.wait_group %0;" :: "n"(N) : "memory");
}

// Convert [64][128] f32 -> fp16 hi+lo smem tiles. Vectorized: 8 floats/thread/iter,
// one STS.128 hi + one STS.128 lo.
__device__ __forceinline__ void conv64_hl(char* hi, char* lo, const float* __restrict__ src, int tid) {
    const float4* s4 = (const float4*)src;
    #pragma unroll
    for (int it = 0; it < 4; ++it) {
        int li = tid + 256 * it;          // < 1024; thread owns floats [8li, 8li+8)
        int r = li >> 4, c8 = li & 15;
        float4 v0 = s4[2 * li], v1 = s4[2 * li + 1];
        uint4 h = make_uint4(packhf(v0.x, v0.y), packhf(v0.z, v0.w),
                             packhf(v1.x, v1.y), packhf(v1.z, v1.w));
        uint4 l = make_uint4(packhf(hlo(v0.x), hlo(v0.y)), packhf(hlo(v0.z), hlo(v0.w)),
                             packhf(hlo(v1.x), hlo(v1.y)), packhf(hlo(v1.z), hlo(v1.w)));
        int off = r * (SH * 2) + 16 * c8;
        *(uint4*)(hi + off) = h;
        *(uint4*)(lo + off) = l;
    }
}
// Convert [64][128] f32 -> fp16 hi-only smem tile (A-side), vectorized
__device__ __forceinline__ void conv64_h(char* hi, const float* __restrict__ src, int tid) {
    const float4* s4 = (const float4*)src;
    #pragma unroll
    for (int it = 0; it < 4; ++it) {
        int li = tid + 256 * it;
        int r = li >> 4, c8 = li & 15;
        float4 v0 = s4[2 * li], v1 = s4[2 * li + 1];
        uint4 h = make_uint4(packhf(v0.x, v0.y), packhf(v0.z, v0.w),
                             packhf(v1.x, v1.y), packhf(v1.z, v1.w));
        *(uint4*)(hi + r * (SH * 2) + 16 * c8) = h;
    }
}

// ---- prologue: W -> fp16 hi images ----
__global__ void conv_w_kernel(const float* __restrict__ Wg) {
    int idx = blockIdx.x * blockDim.x + threadIdx.x;
    if (idx >= 4096) return;
    int p = idx >> 11, li = idx & 2047;
    int r = li >> 5, c4 = li & 31;
    const float4* s4 = (const float4*)(Wg + p * 64 * NE);
    float4 v = s4[li];
    uint2 h = make_uint2(packhf(v.x, v.y), packhf(v.z, v.w));
    *(uint2*)(g_Wbf[p] + r * (SH * 2) + 8 * c4) = h;
}

__global__ void __launch_bounds__(256, 3)
sent_attn_hmma3(const float* __restrict__ Xg, const float* __restrict__ Wg,
                const int* __restrict__ lens, float* __restrict__ out)
{
    extern __shared__ char sm[];
    const u32 sb = sm2u(sm);
    const int tid = threadIdx.x, lane = tid & 31, wid = tid >> 5;
    const int mg = wid >> 2, ng = wid & 3;        // warp tile rows 32*mg, cols 32*ng
    const int g = lane >> 2, tig = lane & 3;
    const int qc = blockIdx.x, bd = blockIdx.y;   // qc in 0..3 (64-query chunks)
    const float* X = Xg + (size_t)bd * NS * NE;
    const int L = lens[bd];

    const int arow = (lane & 15);
    const int acol8 = (lane >> 4) << 3;

    // hoisted LDSM base addresses
    const u32 aA0 = sb + R_AH + (u32)(((32 * mg + arow) * SH + acol8) * 2);
    const u32 aB2 = sb + R_BH + (u32)(((16 * ng + arow) * SH + acol8) * 2);
    const u32 aBT = sb + R_BH + (u32)((arow * SH + 32 * ng + acol8) * 2);
    const u32 aP0 = sb + R_PH + (u32)(((32 * mg + arow) * PSTR + acol8) * 2);

    // ---- W pass-0 hi image via cp.async, overlapped with Xq hi conversion ----
    for (int li = tid; li < 1088; li += 256)      // 17408B / 16
        cpa16(sb + R_BH + li * 16, g_Wbf[0] + li * 16);
    cpa_commit();
    conv64_h(sm + R_AH, X + qc * 64 * NE, tid);
    cpa_wait<0>();
    __syncthreads();

    // ================= GEMM1: XW = Xq_hi @ W_hi (single term), trans B =================
    float c1[2][4][4];
    #pragma unroll
    for (int mt = 0; mt < 2; ++mt)
        #pragma unroll
        for (int nt = 0; nt < 4; ++nt)
            #pragma unroll
            for (int r = 0; r < 4; ++r) c1[mt][nt][r] = 0.f;

    #pragma unroll
    for (int p = 0; p < 2; ++p) {
        #pragma unroll
        for (int k0 = 0; k0 < 4; ++k0) {
            u32 ah[2][4];
            #pragma unroll
            for (int mt = 0; mt < 2; ++mt)
                ldsm_x4(ah[mt], aA0 + (u32)((16 * mt * SH + p * 64 + k0 * 16) * 2));
            u32 bh[8];
            {
                u32 b0 = aBT + (u32)(k0 * 16 * SH * 2);
                ldsm_x4t(bh, b0); ldsm_x4t(bh + 4, b0 + 32);
            }
            #pragma unroll
            for (int mt = 0; mt < 2; ++mt)
                #pragma unroll
                for (int nt = 0; nt < 4; ++nt)
                    mma_hf(c1[mt][nt], ah[mt], bh[2 * nt], bh[2 * nt + 1]);
        }
        if (p == 0) {
            __syncthreads();                           // W0 reads done
            for (int li = tid; li < 1088; li += 256)
                cpa16(sb + R_BH + li * 16, g_Wbf[1] + li * 16);
            cpa_commit();
            cpa_wait<0>();
            __syncthreads();
        }
    }
    __syncthreads();   // RACE FIX: sibling warps read A's full row-band in GEMM1

    // ---- epilogue 1: XW hi overwrites region A ----
    #pragma unroll
    for (int mt = 0; mt < 2; ++mt)
        #pragma unroll
        for (int nt = 0; nt < 4; ++nt)
            #pragma unroll
            for (int h = 0; h < 2; ++h) {
                int row = 32 * mg + 16 * mt + g + 8 * h;
                int col = 32 * ng + 8 * nt + 2 * tig;
                *(u32*)(sm + R_AH + (row * SH + col) * 2) = packhf(c1[mt][nt][2 * h], c1[mt][nt][2 * h + 1]);
            }

    // ---- persistent accumulators ----
    float c3[2][4][4];
    #pragma unroll
    for (int mt = 0; mt < 2; ++mt)
        #pragma unroll
        for (int nt = 0; nt < 4; ++nt)
            #pragma unroll
            for (int r = 0; r < 4; ++r) c3[mt][nt][r] = 0.f;
    float sumM[2][2];
    sumM[0][0] = sumM[0][1] = sumM[1][0] = sumM[1][1] = 0.f;

    const int nch = min(4, (L + 63) >> 6);   // 64-key chunks; keys >= L contribute 0
    for (int ct = 0; ct < nch; ++ct) {
        __syncthreads();                     // epi1 visible / prior B,P reads done
        conv64_hl(sm + R_BH, sm + R_BL, X + ct * 64 * NE, tid);   // keys hi+lo
        __syncthreads();

        // ===== GEMM2: logits = XWh @ keys^T (2-term: keys-lo kept — error amplifies
        //        through tanh->exp here), non-trans B, n-tile 16 =====
        float c2[2][2][4];
        #pragma unroll
        for (int mt = 0; mt < 2; ++mt)
            #pragma unroll
            for (int nt = 0; nt < 2; ++nt)
                #pragma unroll
                for (int r = 0; r < 4; ++r) c2[mt][nt][r] = 0.f;

        #pragma unroll
        for (int k0 = 0; k0 < 8; ++k0) {
            u32 ah[2][4];
            #pragma unroll
            for (int mt = 0; mt < 2; ++mt)
                ldsm_x4(ah[mt], aA0 + (u32)((16 * mt * SH + k0 * 16) * 2));
            u32 bh[4], bl[4];
            {
                u32 bad = aB2 + (u32)(k0 * 16 * 2);
                ldsm_x4(bh, bad);
                ldsm_x4(bl, bad + T_A);
            }
            #pragma unroll
            for (int mt = 0; mt < 2; ++mt)
                #pragma unroll
                for (int nt = 0; nt < 2; ++nt) {
                    mma_hf(c2[mt][nt], ah[mt], bh[nt], bh[nt + 2]);
                    mma_hf(c2[mt][nt], ah[mt], bl[nt], bl[nt + 2]);
                }
        }

        // ---- epilogue 2: exp(tanh), mask, row sums, P hi ----
        #pragma unroll
        for (int mt = 0; mt < 2; ++mt)
            #pragma unroll
            for (int nt = 0; nt < 2; ++nt)
                #pragma unroll
                for (int h = 0; h < 2; ++h) {
                    int row = 32 * mg + 16 * mt + g + 8 * h;
                    int col = 16 * ng + 8 * nt + 2 * tig;
                    int t = ct * 64 + col;
                    float p0 = expTanh(c2[mt][nt][2 * h]);
                    float p1 = expTanh(c2[mt][nt][2 * h + 1]);
                    if (t     >= L) p0 = 0.f;
                    if (t + 1 >= L) p1 = 0.f;
                    sumM[mt][h] += p0 + p1;
                    *(u32*)(sm + R_PH + (row * PSTR + col) * 2) = packhf(p0, p1);
                }
        __syncthreads();   // P complete (cross-warp k reads in GEMM3)

        // ===== GEMM3: att += Ph @ keys-hi (single term), trans B, k = 64 =====
        #pragma unroll
        for (int k0 = 0; k0 < 4; ++k0) {
            u32 ah[2][4];
            #pragma unroll
            for (int mt = 0; mt < 2; ++mt)
                ldsm_x4(ah[mt], aP0 + (u32)((16 * mt * PSTR + k0 * 16) * 2));
            u32 bh[8];
            {
                u32 b0 = aBT + (u32)(k0 * 16 * SH * 2);
                ldsm_x4t(bh, b0); ldsm_x4t(bh + 4, b0 + 32);
            }
            #pragma unroll
            for (int mt = 0; mt < 2; ++mt)
                #pragma unroll
                for (int nt = 0; nt < 4; ++nt)
                    mma_hf(c3[mt][nt], ah[mt], bh[2 * nt], bh[2 * nt + 1]);
        }
    }

    // ---- row-sum reduction ----
    #pragma unroll
    for (int mt = 0; mt < 2; ++mt)
        #pragma unroll
        for (int h = 0; h < 2; ++h) {
            float v = sumM[mt][h];
            v += __shfl_xor_sync(0xffffffffu, v, 1);
            v += __shfl_xor_sync(0xffffffffu, v, 2);
            if (tig == 0) {
                int row = 32 * mg + 16 * mt + g + 8 * h;
                ((float*)(sm + R_RM))[row * 4 + ng] = v;
            }
        }
    __syncthreads();
    if (tid < 64) {
        const float* rm = (const float*)(sm + R_RM);
        float s = rm[tid * 4] + rm[tid * 4 + 1] + rm[tid * 4 + 2] + rm[tid * 4 + 3];
        ((float*)(sm + R_INV))[tid] = 1.0f / s;
    }
    __syncthreads();

    // ---- output: renormalize, STG.64 ----
    float* obase = out + ((size_t)bd * NS + qc * 64) * NE;
    const float* invp = (const float*)(sm + R_INV);
    #pragma unroll
    for (int mt = 0; mt < 2; ++mt)
        #pragma unroll
        for (int h = 0; h < 2; ++h) {
            int row = 32 * mg + 16 * mt + g + 8 * h;
            float iv = invp[row];
            #pragma unroll
            for (int nt = 0; nt < 4; ++nt) {
                int col = 32 * ng + 8 * nt + 2 * tig;
                float2 v = make_float2(c3[mt][nt][2 * h] * iv, c3[mt][nt][2 * h + 1] * iv);
                *(float2*)(obase + row * NE + col) = v;
            }
        }
}

extern "C" void kernel_launch(void* const* d_in, const int* in_sizes, int n_in,
                              void* d_out, int out_size)
{
    const float* X    = (const float*)d_in[0];   // words_enc (8,64,256,128) f32
    const float* W    = (const float*)d_in[1];   // W (128,128) f32
    const int*   lens = (const int*)d_in[2];     // valid_words_len (8,64) i32
    float*       out  = (float*)d_out;           // (8,64,256,128) f32

    conv_w_kernel<<<16, 256>>>(W);               // preconvert W fp16 hi images

    cudaFuncSetAttribute(sent_attn_hmma3, cudaFuncAttributeMaxDynamicSharedMemorySize, SMEM_BYTES);
    dim3 grid(4, NBD, 1);   // 4 query chunks x 512 sentences
    dim3 block(256, 1, 1);
    sent_attn_hmma3<<<grid, block, SMEM_BYTES>>>(X, W, lens, out);
}

// round 14
// speedup vs baseline: 5.9784x; 1.0688x over previous
#include <cuda_runtime.h>
#include <cuda_fp16.h>
#include <stdint.h>

#define NBD 512
#define NS  256
#define NE  128
#define SH   136                // halves per A/B tile row (272B)
#define PSTR 72                 // halves per P tile row (144B)
#define T64  (64*SH*2)          // 17408 B per 64-row fp16 tile
#define T128 (128*SH*2)         // 34816 B per 128-row fp16 tile

// smem regions (byte offsets)
#define R_AH 0                  // Xq -> XW hi [128 rows]
#define R_KH (R_AH + T128)      // W image [128 rows] / keys hi [64 rows]
#define R_KL (R_KH + T64)       // (W rows 64-127) / keys lo
#define R_PH (R_KL + T64)       // P hi [128 rows, PSTR]
#define R_RM (R_PH + 128*PSTR*2) // 128*2 f32 row-sum partials
#define R_INV (R_RM + 1024)     // 128 f32
#define SMEM_BYTES (R_INV + 512 + 256)   // ~89.9KB -> 2 CTAs/SM

typedef uint32_t u32;

// W preconverted fp16 hi image, 128 rows, byte-identical to R_KH..R_KL layout
__device__ __align__(16) char g_Wh[T128];

__device__ __forceinline__ u32 sm2u(const void* p) {
    u32 a;
    asm("{ .reg .u64 t; cvta.to.shared.u64 t, %1; cvt.u32.u64 %0, t; }" : "=r"(a) : "l"(p));
    return a;
}
__device__ __forceinline__ u32 packhf(float a, float b) {
    __half2 h = __floats2half2_rn(a, b);
    return *(u32*)&h;
}
__device__ __forceinline__ float hlo(float x) {
    return x - __half2float(__float2half_rn(x));
}
// Accurate expTanh: exp(1 - 2/(e^{2x}+1))
__device__ __forceinline__ float expTanh(float x) {
    float e2 = __expf(2.0f * x);
    float th = 1.0f - __fdividef(2.0f, e2 + 1.0f);
    return __expf(th);
}
__device__ __forceinline__ void ldsm_x4(u32* r, u32 a) {
    asm volatile("ldmatrix.sync.aligned.m8n8.x4.shared.b16 {%0,%1,%2,%3}, [%4];"
                 : "=r"(r[0]), "=r"(r[1]), "=r"(r[2]), "=r"(r[3]) : "r"(a));
}
__device__ __forceinline__ void ldsm_x4t(u32* r, u32 a) {
    asm volatile("ldmatrix.sync.aligned.m8n8.x4.trans.shared.b16 {%0,%1,%2,%3}, [%4];"
                 : "=r"(r[0]), "=r"(r[1]), "=r"(r[2]), "=r"(r[3]) : "r"(a));
}
__device__ __forceinline__ void mma_hf(float* c, const u32* a, u32 b0, u32 b1) {
    asm volatile(
        "mma.sync.aligned.m16n8k16.row.col.f32.f16.f16.f32 "
        "{%0,%1,%2,%3}, {%4,%5,%6,%7}, {%8,%9}, {%0,%1,%2,%3};"
        : "+f"(c[0]), "+f"(c[1]), "+f"(c[2]), "+f"(c[3])
        : "r"(a[0]), "r"(a[1]), "r"(a[2]), "r"(a[3]), "r"(b0), "r"(b1));
}
__device__ __forceinline__ void cpa16(u32 smem, const void* g) {
    asm volatile("cp.async.cg.shared.global [%0], [%1], 16;" :: "r"(smem), "l"(g));
}
__device__ __forceinline__ void cpa_commit() { asm volatile("cp.async.commit_group;" ::: "memory"); }
template<int N> __device__ __forceinline__ void cpa_wait() {
    asm volatile("cp.async.wait_group %0;" :: "n"(N) : "memory");
}

// [64][128] f32 -> fp16 hi+lo tiles (keys). 8 floats/thread/iter, STS.128 each.
__device__ __forceinline__ void conv64_hl(char* hi, char* lo, const float* __restrict__ src, int tid) {
    const float4* s4 = (const float4*)src;
    #pragma unroll
    for (int it = 0; it < 4; ++it) {
        int li = tid + 256 * it;          // < 1024
        int r = li >> 4, c8 = li & 15;
        float4 v0 = s4[2 * li], v1 = s4[2 * li + 1];
        uint4 h = make_uint4(packhf(v0.x, v0.y), packhf(v0.z, v0.w),
                             packhf(v1.x, v1.y), packhf(v1.z, v1.w));
        uint4 l = make_uint4(packhf(hlo(v0.x), hlo(v0.y)), packhf(hlo(v0.z), hlo(v0.w)),
                             packhf(hlo(v1.x), hlo(v1.y)), packhf(hlo(v1.z), hlo(v1.w)));
        int off = r * (SH * 2) + 16 * c8;
        *(uint4*)(hi + off) = h;
        *(uint4*)(lo + off) = l;
    }
}
// [128][128] f32 -> fp16 hi-only tile (Xq)
__device__ __forceinline__ void conv128_h(char* hi, const float* __restrict__ src, int tid) {
    const float4* s4 = (const float4*)src;
    #pragma unroll
    for (int it = 0; it < 8; ++it) {
        int li = tid + 256 * it;          // < 2048
        int r = li >> 4, c8 = li & 15;
        float4 v0 = s4[2 * li], v1 = s4[2 * li + 1];
        uint4 h = make_uint4(packhf(v0.x, v0.y), packhf(v0.z, v0.w),
                             packhf(v1.x, v1.y), packhf(v1.z, v1.w));
        *(uint4*)(hi + r * (SH * 2) + 16 * c8) = h;
    }
}

// ---- prologue: W -> fp16 hi image (128 rows) ----
__global__ void conv_w_kernel(const float* __restrict__ Wg) {
    int li = blockIdx.x * blockDim.x + threadIdx.x;
    if (li >= 4096) return;
    int r = li >> 5, c4 = li & 31;
    const float4* s4 = (const float4*)Wg;
    float4 v = s4[li];
    uint2 h = make_uint2(packhf(v.x, v.y), packhf(v.z, v.w));
    *(uint2*)(g_Wh + r * (SH * 2) + 8 * c4) = h;
}

__global__ void __launch_bounds__(256, 2)
sent_attn_hmma4(const float* __restrict__ Xg, const float* __restrict__ Wg,
                const int* __restrict__ lens, float* __restrict__ out)
{
    extern __shared__ char sm[];
    const u32 sb = sm2u(sm);
    const int tid = threadIdx.x, lane = tid & 31, wid = tid >> 5;
    const int mg = wid >> 1;           // 0..3: 32-row query band
    const int ng = wid & 1;            // 0..1: col group (64 for G1/G3, 32 for G2)
    const int g = lane >> 2, tig = lane & 3;
    const int qc = blockIdx.x, bd = blockIdx.y;   // qc 0..1 (128-query chunks)
    const float* X = Xg + (size_t)bd * NS * NE;
    const int L = lens[bd];

    const int arow = (lane & 15);
    const int acol8 = (lane >> 4) << 3;

    // hoisted LDSM bases
    const u32 aA0 = sb + R_AH + (u32)(((32 * mg + arow) * SH + acol8) * 2);   // A / XW rows
    const u32 aW  = sb + R_KH + (u32)((arow * SH + 64 * ng + acol8) * 2);     // G1 B (W trans) & G3 B (keys trans)
    const u32 aK2 = sb + R_KH + (u32)(((32 * ng + arow) * SH + acol8) * 2);   // G2 B (keys non-trans)
    const u32 aP0 = sb + R_PH + (u32)(((32 * mg + arow) * PSTR + acol8) * 2); // G3 A (P)

    // ---- W image (34816B) via cp.async into K region, overlapped with Xq conv ----
    for (int li = tid; li < 2176; li += 256)
        cpa16(sb + R_KH + li * 16, g_Wh + li * 16);
    cpa_commit();
    conv128_h(sm + R_AH, X + qc * 128 * NE, tid);
    cpa_wait<0>();
    __syncthreads();

    // ======= GEMM1: XW = Xq_hi @ W_hi, warp tile 32x64, trans B, k=128 =======
    float c1[2][8][4];
    #pragma unroll
    for (int mt = 0; mt < 2; ++mt)
        #pragma unroll
        for (int nt = 0; nt < 8; ++nt)
            #pragma unroll
            for (int r = 0; r < 4; ++r) c1[mt][nt][r] = 0.f;

    #pragma unroll
    for (int k0 = 0; k0 < 8; ++k0) {
        u32 ah[2][4];
        #pragma unroll
        for (int mt = 0; mt < 2; ++mt)
            ldsm_x4(ah[mt], aA0 + (u32)((16 * mt * SH + k0 * 16) * 2));
        u32 bw[16];
        {
            u32 b0 = aW + (u32)(k0 * 16 * SH * 2);
            ldsm_x4t(bw, b0); ldsm_x4t(bw + 4, b0 + 32);
            ldsm_x4t(bw + 8, b0 + 64); ldsm_x4t(bw + 12, b0 + 96);
        }
        #pragma unroll
        for (int mt = 0; mt < 2; ++mt)
            #pragma unroll
            for (int nt = 0; nt < 8; ++nt)
                mma_hf(c1[mt][nt], ah[mt], bw[2 * nt], bw[2 * nt + 1]);
    }
    __syncthreads();   // RACE FIX: sibling warp (same mg, other ng) still reading A rows

    // ---- epilogue 1: XW hi overwrites region A ----
    #pragma unroll
    for (int mt = 0; mt < 2; ++mt)
        #pragma unroll
        for (int nt = 0; nt < 8; ++nt)
            #pragma unroll
            for (int h = 0; h < 2; ++h) {
                int row = 32 * mg + 16 * mt + g + 8 * h;
                int col = 64 * ng + 8 * nt + 2 * tig;
                *(u32*)(sm + R_AH + (row * SH + col) * 2) = packhf(c1[mt][nt][2 * h], c1[mt][nt][2 * h + 1]);
            }

    // ---- persistent accumulators ----
    float c3[2][8][4];
    #pragma unroll
    for (int mt = 0; mt < 2; ++mt)
        #pragma unroll
        for (int nt = 0; nt < 8; ++nt)
            #pragma unroll
            for (int r = 0; r < 4; ++r) c3[mt][nt][r] = 0.f;
    float sumM[2][2];
    sumM[0][0] = sumM[0][1] = sumM[1][0] = sumM[1][1] = 0.f;

    const int nch = min(4, (L + 63) >> 6);   // 64-key chunks
    for (int ct = 0; ct < nch; ++ct) {
        __syncthreads();                     // epi1 visible / prior K,P reads done
        conv64_hl(sm + R_KH, sm + R_KL, X + ct * 64 * NE, tid);   // keys hi+lo (once per 128q!)
        __syncthreads();

        // ===== GEMM2: logits[128][64] = XWh @ keys^T (2-term), warp tile 32x32 =====
        float c2[2][4][4];
        #pragma unroll
        for (int mt = 0; mt < 2; ++mt)
            #pragma unroll
            for (int nt = 0; nt < 4; ++nt)
                #pragma unroll
                for (int r = 0; r < 4; ++r) c2[mt][nt][r] = 0.f;

        #pragma unroll
        for (int k0 = 0; k0 < 8; ++k0) {
            u32 ah[2][4];
            #pragma unroll
            for (int mt = 0; mt < 2; ++mt)
                ldsm_x4(ah[mt], aA0 + (u32)((16 * mt * SH + k0 * 16) * 2));
            // hi term (rows 32ng..+32 of keys)
            {
                u32 kb[8];
                u32 b0 = aK2 + (u32)(k0 * 32);
                ldsm_x4(kb, b0);
                ldsm_x4(kb + 4, b0 + (u32)(16 * SH * 2));
                #pragma unroll
                for (int mt = 0; mt < 2; ++mt)
                    #pragma unroll
                    for (int nt = 0; nt < 4; ++nt) {
                        int q = nt >> 1, r2 = nt & 1;
                        mma_hf(c2[mt][nt], ah[mt], kb[4 * q + r2], kb[4 * q + r2 + 2]);
                    }
            }
            // lo term
            {
                u32 kb[8];
                u32 b0 = aK2 + (u32)(k0 * 32) + (u32)T64;
                ldsm_x4(kb, b0);
                ldsm_x4(kb + 4, b0 + (u32)(16 * SH * 2));
                #pragma unroll
                for (int mt = 0; mt < 2; ++mt)
                    #pragma unroll
                    for (int nt = 0; nt < 4; ++nt) {
                        int q = nt >> 1, r2 = nt & 1;
                        mma_hf(c2[mt][nt], ah[mt], kb[4 * q + r2], kb[4 * q + r2 + 2]);
                    }
            }
        }

        // ---- epilogue 2: exp(tanh), mask, row sums, P hi ----
        #pragma unroll
        for (int mt = 0; mt < 2; ++mt)
            #pragma unroll
            for (int nt = 0; nt < 4; ++nt)
                #pragma unroll
                for (int h = 0; h < 2; ++h) {
                    int row = 32 * mg + 16 * mt + g + 8 * h;
                    int col = 32 * ng + 8 * nt + 2 * tig;
                    int t = ct * 64 + col;
                    float p0 = expTanh(c2[mt][nt][2 * h]);
                    float p1 = expTanh(c2[mt][nt][2 * h + 1]);
                    if (t     >= L) p0 = 0.f;
                    if (t + 1 >= L) p1 = 0.f;
                    sumM[mt][h] += p0 + p1;
                    *(u32*)(sm + R_PH + (row * PSTR + col) * 2) = packhf(p0, p1);
                }
        __syncthreads();   // P complete (cross-warp k reads in GEMM3)

        // ===== GEMM3: att += Ph @ keys-hi, warp tile 32x64, trans B, k=64 =====
        #pragma unroll
        for (int k0 = 0; k0 < 4; ++k0) {
            u32 ah[2][4];
            #pragma unroll
            for (int mt = 0; mt < 2; ++mt)
                ldsm_x4(ah[mt], aP0 + (u32)((16 * mt * PSTR + k0 * 16) * 2));
            u32 bw[16];
            {
                u32 b0 = aW + (u32)(k0 * 16 * SH * 2);
                ldsm_x4t(bw, b0); ldsm_x4t(bw + 4, b0 + 32);
                ldsm_x4t(bw + 8, b0 + 64); ldsm_x4t(bw + 12, b0 + 96);
            }
            #pragma unroll
            for (int mt = 0; mt < 2; ++mt)
                #pragma unroll
                for (int nt = 0; nt < 8; ++nt)
                    mma_hf(c3[mt][nt], ah[mt], bw[2 * nt], bw[2 * nt + 1]);
        }
    }

    // ---- row-sum reduction (2 ng halves per row) ----
    #pragma unroll
    for (int mt = 0; mt < 2; ++mt)
        #pragma unroll
        for (int h = 0; h < 2; ++h) {
            float v = sumM[mt][h];
            v += __shfl_xor_sync(0xffffffffu, v, 1);
            v += __shfl_xor_sync(0xffffffffu, v, 2);
            if (tig == 0) {
                int row = 32 * mg + 16 * mt + g + 8 * h;
                ((float*)(sm + R_RM))[row * 2 + ng] = v;
            }
        }
    __syncthreads();
    if (tid < 128) {
        const float* rm = (const float*)(sm + R_RM);
        ((float*)(sm + R_INV))[tid] = 1.0f / (rm[tid * 2] + rm[tid * 2 + 1]);
    }
    __syncthreads();

    // ---- output: renormalize, STG.64 ----
    float* obase = out + ((size_t)bd * NS + qc * 128) * NE;
    const float* invp = (const float*)(sm + R_INV);
    #pragma unroll
    for (int mt = 0; mt < 2; ++mt)
        #pragma unroll
        for (int h = 0; h < 2; ++h) {
            int row = 32 * mg + 16 * mt + g + 8 * h;
            float iv = invp[row];
            #pragma unroll
            for (int nt = 0; nt < 8; ++nt) {
                int col = 64 * ng + 8 * nt + 2 * tig;
                float2 v = make_float2(c3[mt][nt][2 * h] * iv, c3[mt][nt][2 * h + 1] * iv);
                *(float2*)(obase + row * NE + col) = v;
            }
        }
}

extern "C" void kernel_launch(void* const* d_in, const int* in_sizes, int n_in,
                              void* d_out, int out_size)
{
    const float* X    = (const float*)d_in[0];   // words_enc (8,64,256,128) f32
    const float* W    = (const float*)d_in[1];   // W (128,128) f32
    const int*   lens = (const int*)d_in[2];     // valid_words_len (8,64) i32
    float*       out  = (float*)d_out;           // (8,64,256,128) f32

    conv_w_kernel<<<16, 256>>>(W);               // preconvert W fp16 hi image

    cudaFuncSetAttribute(sent_attn_hmma4, cudaFuncAttributeMaxDynamicSharedMemorySize, SMEM_BYTES);
    dim3 grid(2, NBD, 1);   // 2 query chunks x 512 sentences
    dim3 block(256, 1, 1);
    sent_attn_hmma4<<<grid, block, SMEM_BYTES>>>(X, W, lens, out);
}